// round 8
// baseline (speedup 1.0000x reference)
#include <cuda_runtime.h>
#include <cuda_bf16.h>
#include <math.h>
#include <stdint.h>

#define B_ 64
#define T_ 512
#define D_ 1024
#define H_ 1024
#define G_ 4096

// ---------------- device scratch (allocation-free rule) ----------------
__device__ float g_xg[(size_t)T_ * B_ * G_];            // [T][B][4H] pre-activations
__device__ __nv_bfloat16 g_hh[2][128 * H_];             // ping-pong; rows 0-63 h_hi, 64-127 h_lo
__device__ __nv_bfloat16 g_WW[(size_t)G_ * 2 * H_];     // [4096][2048]: 0-1023 W_hi, 1024-2047 W_lo
__device__ int g_flags[128];                            // grid barrier flags

#define SWZ(off) ((off) ^ (((off) >> 3) & 0x70))

__device__ __forceinline__ uint32_t smem_to_u32(const void* p) {
    uint32_t a;
    asm("{ .reg .u64 t; cvta.to.shared.u64 t, %1; cvt.u32.u64 %0, t; }" : "=r"(a) : "l"(p));
    return a;
}

__device__ __forceinline__ void ldsm_x4(uint32_t& r0, uint32_t& r1, uint32_t& r2,
                                        uint32_t& r3, uint32_t addr) {
    asm volatile("ldmatrix.sync.aligned.m8n8.x4.shared.b16 {%0,%1,%2,%3}, [%4];"
                 : "=r"(r0), "=r"(r1), "=r"(r2), "=r"(r3) : "r"(addr));
}

__device__ __forceinline__ void hmma16816(float* d, uint32_t a0, uint32_t a1,
                                          uint32_t a2, uint32_t a3,
                                          uint32_t b0, uint32_t b1) {
    asm volatile(
        "mma.sync.aligned.m16n8k16.row.col.f32.bf16.bf16.f32 "
        "{%0,%1,%2,%3}, {%4,%5,%6,%7}, {%8,%9}, {%0,%1,%2,%3};"
        : "+f"(d[0]), "+f"(d[1]), "+f"(d[2]), "+f"(d[3])
        : "r"(a0), "r"(a1), "r"(a2), "r"(a3), "r"(b0), "r"(b1));
}

__device__ __forceinline__ void cp_async16(uint32_t dst, const void* src) {
    asm volatile("cp.async.cg.shared.global [%0], [%1], 16;"
                 :: "r"(dst), "l"(src) : "memory");
}
#define CP_COMMIT() asm volatile("cp.async.commit_group;" ::: "memory")
#define CP_WAIT(N)  asm volatile("cp.async.wait_group %0;" :: "n"(N) : "memory")

__device__ __forceinline__ float sigf(float x) {
    return __fdividef(1.f, 1.f + __expf(-x));
}
__device__ __forceinline__ float tanh_fast(float x) {
    x = fminf(fmaxf(x, -15.f), 15.f);
    float e = __expf(2.f * x);
    return __fdividef(e - 1.f, e + 1.f);
}

// ---------------- init kernels ----------------
__global__ void init_state_kernel() {
    int i = blockIdx.x * blockDim.x + threadIdx.x;
    if (i < 128 * H_) g_hh[0][i] = __float2bfloat16(0.f);
    if (i < 128) g_flags[i] = 0;
}

__global__ void build_WW_kernel(const float* __restrict__ W_hh) {
    int i = blockIdx.x * blockDim.x + threadIdx.x;
    if (i < G_ * H_) {
        int row = i >> 10, col = i & 1023;
        float w = W_hh[i];
        __nv_bfloat16 hi = __float2bfloat16(w);
        __nv_bfloat16 lo = __float2bfloat16(w - __bfloat162float(hi));
        g_WW[(size_t)row * 2048 + col] = hi;
        g_WW[(size_t)row * 2048 + 1024 + col] = lo;
    }
}

// ---------------- Phase A: x_gates GEMM (fp32, proven) ----------------
__global__ __launch_bounds__(256) void gemm_xg_kernel(
    const float* __restrict__ feature, const float* __restrict__ W_ih,
    const float* __restrict__ b_ih, const float* __restrict__ b_hh)
{
    __shared__ __align__(16) float As[16][68];
    __shared__ __align__(16) float Bs[16][68];
    int tid = threadIdx.x;
    int tx = tid & 15, ty = tid >> 4;
    int n0 = blockIdx.x * 64;
    int t  = blockIdx.y;
    int lr = tid >> 2;
    int lk = (tid & 3) * 4;

    const float* fptr = feature + ((size_t)lr * T_ + t) * D_ + lk;
    const float* wptr = W_ih + (size_t)(n0 + lr) * D_ + lk;

    float acc[4][4] = {};
    for (int k0 = 0; k0 < D_; k0 += 16) {
        float4 av = *(const float4*)(fptr + k0);
        float4 bv = *(const float4*)(wptr + k0);
        __syncthreads();
        As[lk + 0][lr] = av.x; As[lk + 1][lr] = av.y;
        As[lk + 2][lr] = av.z; As[lk + 3][lr] = av.w;
        Bs[lk + 0][lr] = bv.x; Bs[lk + 1][lr] = bv.y;
        Bs[lk + 2][lr] = bv.z; Bs[lk + 3][lr] = bv.w;
        __syncthreads();
#pragma unroll
        for (int k = 0; k < 16; k++) {
            float4 a4 = *(const float4*)&As[k][ty * 4];
            float4 b4 = *(const float4*)&Bs[k][tx * 4];
            acc[0][0] = fmaf(a4.x, b4.x, acc[0][0]);
            acc[0][1] = fmaf(a4.x, b4.y, acc[0][1]);
            acc[0][2] = fmaf(a4.x, b4.z, acc[0][2]);
            acc[0][3] = fmaf(a4.x, b4.w, acc[0][3]);
            acc[1][0] = fmaf(a4.y, b4.x, acc[1][0]);
            acc[1][1] = fmaf(a4.y, b4.y, acc[1][1]);
            acc[1][2] = fmaf(a4.y, b4.z, acc[1][2]);
            acc[1][3] = fmaf(a4.y, b4.w, acc[1][3]);
            acc[2][0] = fmaf(a4.z, b4.x, acc[2][0]);
            acc[2][1] = fmaf(a4.z, b4.y, acc[2][1]);
            acc[2][2] = fmaf(a4.z, b4.z, acc[2][2]);
            acc[2][3] = fmaf(a4.z, b4.w, acc[2][3]);
            acc[3][0] = fmaf(a4.w, b4.x, acc[3][0]);
            acc[3][1] = fmaf(a4.w, b4.y, acc[3][1]);
            acc[3][2] = fmaf(a4.w, b4.z, acc[3][2]);
            acc[3][3] = fmaf(a4.w, b4.w, acc[3][3]);
        }
    }
    int n = n0 + tx * 4;
    float bx = b_ih[n + 0] + b_hh[n + 0];
    float by_ = b_ih[n + 1] + b_hh[n + 1];
    float bz = b_ih[n + 2] + b_hh[n + 2];
    float bw = b_ih[n + 3] + b_hh[n + 3];
#pragma unroll
    for (int i = 0; i < 4; i++) {
        int b = ty * 4 + i;
        float4 v = make_float4(acc[i][0] + bx, acc[i][1] + by_,
                               acc[i][2] + bz, acc[i][3] + bw);
        *(float4*)(g_xg + ((size_t)t * B_ + b) * G_ + n) = v;
    }
}

// ---------------- Phase B: persistent recurrence, K x N warp split ------------
// Grid = 128 blocks, 512 threads (16 warps). Block bx owns 8 hidden units.
// Warp w = (wq = w>>1, nh = w&1): per stage s it owns the 32-col K-slice at
// s*256 + wq*32, and the 16 gate-cols nh*16..+16. W frags (both passes) for
// that footprint live in 64 registers. Per step: acc(64x16 per warp) +=
// h_hi@W_hi + h_hi@W_lo + h_lo@W_hi; partials merged via ssum[8][64][34].
static constexpr uint32_t OFF_A0 = 0;                   // stage buf 0 (64KB)
static constexpr uint32_t OFF_A1 = 65536;               // stage buf 1 (64KB)
static constexpr uint32_t OFF_S  = 131072;              // ssum [8][64][34] f32
static constexpr uint32_t SMEM_USED = OFF_S + 8 * 64 * 34 * 4;
static constexpr uint32_t SMEM_REQ  = SMEM_USED + 1024;

__global__ __launch_bounds__(512, 1) void lstm_persistent(
    const int* __restrict__ seq_len, float* __restrict__ out)
{
    extern __shared__ char dsm_raw[];
    uint32_t raw = smem_to_u32(dsm_raw);
    uint32_t sbase = (raw + 1023u) & ~1023u;
    char* sm = dsm_raw + (sbase - raw);

    int tid = threadIdx.x;
    int wid = tid >> 5, lane = tid & 31;
    int bx = blockIdx.x;
    int j0 = bx * 8;
    int wq = wid >> 1;            // K-slice 0..7
    int nh = wid & 1;             // N-half 0..1

    // ldmatrix lane addressing
    int q8 = lane >> 3, r8 = lane & 7;
    uint32_t a_lrow = (uint32_t)(r8 + (q8 & 1) * 8);
    uint32_t a_kb   = (uint32_t)((q8 >> 1) * 16);
    uint32_t b_lrow = (uint32_t)(nh * 16 + r8 + (q8 >> 1) * 8);
    uint32_t b_kb   = (uint32_t)((q8 & 1) * 16);

    // ---- load W fragments into registers (once): wr[stage][kk][pass][nt][2] ----
    uint32_t wr[4][2][2][2][2];
    {
        int rr = tid >> 4;                    // 0..31 gate-row
        int colB = (tid & 15) * 8;            // 0..120
        int gn = (rr >> 3) * H_ + j0 + (rr & 7);
        const __nv_bfloat16* wrow = g_WW + (size_t)gn * 2048;
#pragma unroll
        for (int ch = 0; ch < 2; ch++) {      // pass: 0=hi, 1=lo
            __syncthreads();
            // stage 32 rows x 1024 cols into 16 subtiles of [32 x 64] (4KB) at OFF_A0
#pragma unroll
            for (int it = 0; it < 8; it++) {
                int col = it * 128 + colB;
                uint4 v = *(const uint4*)(wrow + ch * 1024 + col);
                *(uint4*)(sm + OFF_A0 + (uint32_t)((col >> 6) * 4096)
                          + SWZ((uint32_t)(rr * 128 + (col & 63) * 2))) = v;
            }
            __syncthreads();
#pragma unroll
            for (int s = 0; s < 4; s++)
#pragma unroll
                for (int kk = 0; kk < 2; kk++) {
                    int scol = s * 256 + wq * 32 + kk * 16;
                    uint32_t addr = sbase + OFF_A0 + (uint32_t)((scol >> 6) * 4096) +
                        SWZ(b_lrow * 128 + (uint32_t)((scol & 63) * 2) + b_kb);
                    ldsm_x4(wr[s][kk][ch][0][0], wr[s][kk][ch][0][1],
                            wr[s][kk][ch][1][0], wr[s][kk][ch][1][1], addr);
                }
        }
    }
    __syncthreads();

    // cp.async A-staging: thread covers colEl = (tid&31)*8, rows (tid>>5)+16k
    int colEl = (lane) * 8;                  // 0..248 (lane = tid&31)
    int rA0 = tid >> 5;                      // 0..15
    uint32_t a_dst = (uint32_t)((colEl >> 6) * 16384);
    uint32_t a_cin2 = (uint32_t)((colEl & 63) * 2);

    // per-warp A ldsm constants (kk = 0,1)
    uint32_t asub0 = (uint32_t)(((wq * 32) >> 6) * 16384);
    uint32_t acin0 = (uint32_t)(((wq * 32) & 63) * 2) + a_kb;
    uint32_t asub1 = (uint32_t)(((wq * 32 + 16) >> 6) * 16384);
    uint32_t acin1 = (uint32_t)(((wq * 32 + 16) & 63) * 2) + a_kb;

    // epilogue: 1 item per thread
    int eb = tid >> 3, eu = tid & 7;
    int ej = j0 + eu;
    int sl = seq_len[eb];
    float c_reg = 0.f;

    float* ssum = (float*)(sm + OFF_S);
    volatile int* flags = (volatile int*)g_flags;

#pragma unroll 1
    for (int t = 0; t < T_; t++) {
        const __nv_bfloat16* __restrict__ hin = g_hh[t & 1];
        __nv_bfloat16* __restrict__ hout = g_hh[(t + 1) & 1];

        // prefetch xg for epilogue
        float xr[4];
        {
            const float* xgb = g_xg + ((size_t)t * B_ + eb) * G_ + ej;
#pragma unroll
            for (int g4 = 0; g4 < 4; g4++) xr[g4] = xgb[g4 * H_];
        }

        // issue stage 0
        {
            const __nv_bfloat16* src = hin + (size_t)rA0 * H_ + colEl;
            uint32_t d0 = sbase + OFF_A0 + a_dst;
#pragma unroll
            for (int k = 0; k < 8; k++) {
                int row = rA0 + 16 * k;
                cp_async16(d0 + SWZ((uint32_t)(row * 128) + a_cin2),
                           src + (size_t)(16 * k) * H_);
            }
            CP_COMMIT();
        }

        float acc[4][2][4];
#pragma unroll
        for (int mt = 0; mt < 4; mt++)
#pragma unroll
            for (int nt = 0; nt < 2; nt++)
#pragma unroll
                for (int i = 0; i < 4; i++) acc[mt][nt][i] = 0.f;

#pragma unroll
        for (int s = 0; s < 4; s++) {
            uint32_t abuf = (s & 1) ? OFF_A1 : OFF_A0;
            CP_WAIT(0);                  // stage s data resident
            __syncthreads();             // all warps past stage s-1 compute
            if (s < 3) {                 // issue stage s+1 into other buffer
                uint32_t nbuf = (s & 1) ? OFF_A0 : OFF_A1;
                const __nv_bfloat16* src = hin + (size_t)rA0 * H_ + (s + 1) * 256 + colEl;
                uint32_t d0 = sbase + nbuf + a_dst;
#pragma unroll
                for (int k = 0; k < 8; k++) {
                    int row = rA0 + 16 * k;
                    cp_async16(d0 + SWZ((uint32_t)(row * 128) + a_cin2),
                               src + (size_t)(16 * k) * H_);
                }
                CP_COMMIT();
            }

#pragma unroll
            for (int kk = 0; kk < 2; kk++) {
                uint32_t atile = sbase + abuf + (kk ? asub1 : asub0);
                uint32_t cin2  = kk ? acin1 : acin0;
                uint32_t ah[4][4];
                // hi rows: both passes
#pragma unroll
                for (int mt = 0; mt < 4; mt++)
                    ldsm_x4(ah[mt][0], ah[mt][1], ah[mt][2], ah[mt][3],
                            atile + SWZ((mt * 16 + a_lrow) * 128 + cin2));
#pragma unroll
                for (int p = 0; p < 2; p++)
#pragma unroll
                    for (int mt = 0; mt < 4; mt++)
#pragma unroll
                        for (int nt = 0; nt < 2; nt++)
                            hmma16816(acc[mt][nt], ah[mt][0], ah[mt][1], ah[mt][2], ah[mt][3],
                                      wr[s][kk][p][nt][0], wr[s][kk][p][nt][1]);
                // lo rows: hi pass only
#pragma unroll
                for (int mt = 0; mt < 4; mt++)
                    ldsm_x4(ah[mt][0], ah[mt][1], ah[mt][2], ah[mt][3],
                            atile + SWZ((64 + mt * 16 + a_lrow) * 128 + cin2));
#pragma unroll
                for (int mt = 0; mt < 4; mt++)
#pragma unroll
                    for (int nt = 0; nt < 2; nt++)
                        hmma16816(acc[mt][nt], ah[mt][0], ah[mt][1], ah[mt][2], ah[mt][3],
                                  wr[s][kk][0][nt][0], wr[s][kk][0][nt][1]);
            }
        }
        __syncthreads();   // MMA done everywhere before partial store readers

        // ---- store partials: warp (wq, nh) -> ssum[wq][b][nh*16 + ...] ----
        {
            int r = lane >> 2, c4 = lane & 3;
            float* pp = ssum + wq * (64 * 34);
#pragma unroll
            for (int mt = 0; mt < 4; mt++)
#pragma unroll
                for (int nt = 0; nt < 2; nt++) {
                    int b1 = mt * 16 + r, n = nh * 16 + nt * 8 + c4 * 2;
                    *(float2*)(pp + b1 * 34 + n) =
                        make_float2(acc[mt][nt][0], acc[mt][nt][1]);
                    *(float2*)(pp + (b1 + 8) * 34 + n) =
                        make_float2(acc[mt][nt][2], acc[mt][nt][3]);
                }
        }
        __syncthreads();

        // ---- epilogue: one (b,u) per thread ----
        {
            float gate[4];
#pragma unroll
            for (int g4 = 0; g4 < 4; g4++) {
                int n = g4 * 8 + eu;
                float s0 = 0.f;
#pragma unroll
                for (int w = 0; w < 8; w++)
                    s0 += ssum[w * (64 * 34) + eb * 34 + n];
                gate[g4] = s0 + xr[g4];
            }
            float si = sigf(gate[0]);
            float sf = sigf(gate[1]);
            float tg = tanh_fast(gate[2]);
            float so = sigf(gate[3]);
            c_reg = fmaf(sf, c_reg, si * tg);
            float hn = so * tanh_fast(c_reg);
            __nv_bfloat16 hi = __float2bfloat16(hn);
            hout[eb * H_ + ej] = hi;
            hout[(size_t)(eb + 64) * H_ + ej] = __float2bfloat16(hn - __bfloat162float(hi));
            out[((size_t)eb * T_ + t) * H_ + ej] = (t < sl) ? hn : 0.f;
        }

        // ---- grid barrier: parallel flag poll ----
        __threadfence();
        __syncthreads();
        if (tid == 0) flags[bx] = t + 1;
        if (tid < 128) {
            while (flags[tid] < t + 1) { }
        }
        __syncthreads();
        __threadfence();
    }
}

extern "C" void kernel_launch(void* const* d_in, const int* in_sizes, int n_in,
                              void* d_out, int out_size)
{
    const float* feature = (const float*)d_in[0];
    const float* W_ih    = (const float*)d_in[1];
    const float* W_hh    = (const float*)d_in[2];
    const float* b_ih    = (const float*)d_in[3];
    const float* b_hh    = (const float*)d_in[4];
    const int*   seq_len = (const int*)d_in[5];
    float* out = (float*)d_out;

    cudaFuncSetAttribute(lstm_persistent, cudaFuncAttributeMaxDynamicSharedMemorySize,
                         SMEM_REQ);

    init_state_kernel<<<(128 * H_ + 255) / 256, 256>>>();
    build_WW_kernel<<<(G_ * H_ + 255) / 256, 256>>>(W_hh);
    gemm_xg_kernel<<<dim3(G_ / 64, T_), 256>>>(feature, W_ih, b_ih, b_hh);
    lstm_persistent<<<128, 512, SMEM_REQ>>>(seq_len, out);
}

// round 9
// speedup vs baseline: 1.0361x; 1.0361x over previous
#include <cuda_runtime.h>
#include <cuda_bf16.h>
#include <math.h>
#include <stdint.h>

#define B_ 64
#define T_ 512
#define D_ 1024
#define H_ 1024
#define G_ 4096

// ---------------- device scratch (allocation-free rule) ----------------
__device__ float g_xg[(size_t)T_ * B_ * G_];            // [T][B][4H] pre-activations
// h ping-pong, stored as the SW128-swizzled SMEM image:
// [pp][stage s][subtile][128 rows][128B]; rows 0-63 h_hi, 64-127 h_lo
__device__ __align__(128) uint8_t g_hh2[2][4 * 4 * 128 * 128];
__device__ __nv_bfloat16 g_WW[(size_t)G_ * 2 * H_];     // [4096][2048]: 0-1023 W_hi, 1024-2047 W_lo
__device__ int g_flags[128];                            // grid barrier flags

#define SWZ(off) ((off) ^ (((off) >> 3) & 0x70))

__device__ __forceinline__ uint32_t smem_to_u32(const void* p) {
    uint32_t a;
    asm("{ .reg .u64 t; cvta.to.shared.u64 t, %1; cvt.u32.u64 %0, t; }" : "=r"(a) : "l"(p));
    return a;
}

__device__ __forceinline__ void ldsm_x4(uint32_t& r0, uint32_t& r1, uint32_t& r2,
                                        uint32_t& r3, uint32_t addr) {
    asm volatile("ldmatrix.sync.aligned.m8n8.x4.shared.b16 {%0,%1,%2,%3}, [%4];"
                 : "=r"(r0), "=r"(r1), "=r"(r2), "=r"(r3) : "r"(addr));
}

__device__ __forceinline__ void hmma16816(float* d, uint32_t a0, uint32_t a1,
                                          uint32_t a2, uint32_t a3,
                                          uint32_t b0, uint32_t b1) {
    asm volatile(
        "mma.sync.aligned.m16n8k16.row.col.f32.bf16.bf16.f32 "
        "{%0,%1,%2,%3}, {%4,%5,%6,%7}, {%8,%9}, {%0,%1,%2,%3};"
        : "+f"(d[0]), "+f"(d[1]), "+f"(d[2]), "+f"(d[3])
        : "r"(a0), "r"(a1), "r"(a2), "r"(a3), "r"(b0), "r"(b1));
}

// 1D bulk async copy global -> shared::cta with mbarrier completion (sm_90 PTX)
__device__ __forceinline__ void cp_bulk_g2s(uint32_t dst, const void* src,
                                            uint32_t bytes, uint32_t mbar) {
    asm volatile(
        "cp.async.bulk.shared::cta.global.mbarrier::complete_tx::bytes [%0], [%1], %2, [%3];"
        :: "r"(dst), "l"(src), "r"(bytes), "r"(mbar) : "memory");
}
#define MBARRIER_INIT(addr, cnt) \
    asm volatile("mbarrier.init.shared.b64 [%0], %1;" :: "r"((uint32_t)(addr)), "r"((uint32_t)(cnt)) : "memory")
#define MBARRIER_EXPECT_TX(addr, bytes) \
    asm volatile("mbarrier.arrive.expect_tx.shared.b64 _, [%0], %1;" \
        :: "r"((uint32_t)(addr)), "r"((uint32_t)(bytes)) : "memory")
#define MBARRIER_WAIT_PARITY(mbar_smem_addr, phase_parity) do { \
    uint32_t _mbar = (uint32_t)(mbar_smem_addr); \
    uint32_t _parity = (uint32_t)(phase_parity); \
    uint32_t _done; \
    asm volatile( \
        "{\n\t.reg .pred p;\n\t" \
        "mbarrier.try_wait.parity.acquire.cta.shared::cta.b64 p, [%1], %2;\n\t" \
        "selp.b32 %0, 1, 0, p;\n\t}" \
        : "=r"(_done) : "r"(_mbar), "r"(_parity) : "memory"); \
    if (!_done) { \
        asm volatile( \
            "{\n\t.reg .pred P1;\n\t" \
            "WAIT_LOOP_%=:\n\t" \
            "mbarrier.try_wait.parity.acquire.cta.shared::cta.b64 P1, [%0], %1, 0x989680;\n\t" \
            "@P1 bra.uni WAIT_DONE_%=;\n\t" \
            "bra.uni WAIT_LOOP_%=;\n\t" \
            "WAIT_DONE_%=:\n\t}" \
            :: "r"(_mbar), "r"(_parity) : "memory"); \
    } \
} while(0)

__device__ __forceinline__ float sigf(float x) {
    return __fdividef(1.f, 1.f + __expf(-x));
}
__device__ __forceinline__ float tanh_fast(float x) {
    x = fminf(fmaxf(x, -15.f), 15.f);
    float e = __expf(2.f * x);
    return __fdividef(e - 1.f, e + 1.f);
}

// ---------------- init kernels ----------------
__global__ void init_state_kernel() {
    int i = blockIdx.x * blockDim.x + threadIdx.x;
    // zero both h ping-pong images: 2*256KB = 131072 u32 words
    if (i < 131072) ((uint32_t*)g_hh2)[i] = 0u;
    if (i < 128) g_flags[i] = 0;
}

__global__ void build_WW_kernel(const float* __restrict__ W_hh) {
    int i = blockIdx.x * blockDim.x + threadIdx.x;
    if (i < G_ * H_) {
        int row = i >> 10, col = i & 1023;
        float w = W_hh[i];
        __nv_bfloat16 hi = __float2bfloat16(w);
        __nv_bfloat16 lo = __float2bfloat16(w - __bfloat162float(hi));
        g_WW[(size_t)row * 2048 + col] = hi;
        g_WW[(size_t)row * 2048 + 1024 + col] = lo;
    }
}

// ---------------- Phase A: x_gates GEMM (fp32, proven) ----------------
__global__ __launch_bounds__(256) void gemm_xg_kernel(
    const float* __restrict__ feature, const float* __restrict__ W_ih,
    const float* __restrict__ b_ih, const float* __restrict__ b_hh)
{
    __shared__ __align__(16) float As[16][68];
    __shared__ __align__(16) float Bs[16][68];
    int tid = threadIdx.x;
    int tx = tid & 15, ty = tid >> 4;
    int n0 = blockIdx.x * 64;
    int t  = blockIdx.y;
    int lr = tid >> 2;
    int lk = (tid & 3) * 4;

    const float* fptr = feature + ((size_t)lr * T_ + t) * D_ + lk;
    const float* wptr = W_ih + (size_t)(n0 + lr) * D_ + lk;

    float acc[4][4] = {};
    for (int k0 = 0; k0 < D_; k0 += 16) {
        float4 av = *(const float4*)(fptr + k0);
        float4 bv = *(const float4*)(wptr + k0);
        __syncthreads();
        As[lk + 0][lr] = av.x; As[lk + 1][lr] = av.y;
        As[lk + 2][lr] = av.z; As[lk + 3][lr] = av.w;
        Bs[lk + 0][lr] = bv.x; Bs[lk + 1][lr] = bv.y;
        Bs[lk + 2][lr] = bv.z; Bs[lk + 3][lr] = bv.w;
        __syncthreads();
#pragma unroll
        for (int k = 0; k < 16; k++) {
            float4 a4 = *(const float4*)&As[k][ty * 4];
            float4 b4 = *(const float4*)&Bs[k][tx * 4];
            acc[0][0] = fmaf(a4.x, b4.x, acc[0][0]);
            acc[0][1] = fmaf(a4.x, b4.y, acc[0][1]);
            acc[0][2] = fmaf(a4.x, b4.z, acc[0][2]);
            acc[0][3] = fmaf(a4.x, b4.w, acc[0][3]);
            acc[1][0] = fmaf(a4.y, b4.x, acc[1][0]);
            acc[1][1] = fmaf(a4.y, b4.y, acc[1][1]);
            acc[1][2] = fmaf(a4.y, b4.z, acc[1][2]);
            acc[1][3] = fmaf(a4.y, b4.w, acc[1][3]);
            acc[2][0] = fmaf(a4.z, b4.x, acc[2][0]);
            acc[2][1] = fmaf(a4.z, b4.y, acc[2][1]);
            acc[2][2] = fmaf(a4.z, b4.z, acc[2][2]);
            acc[2][3] = fmaf(a4.z, b4.w, acc[2][3]);
            acc[3][0] = fmaf(a4.w, b4.x, acc[3][0]);
            acc[3][1] = fmaf(a4.w, b4.y, acc[3][1]);
            acc[3][2] = fmaf(a4.w, b4.z, acc[3][2]);
            acc[3][3] = fmaf(a4.w, b4.w, acc[3][3]);
        }
    }
    int n = n0 + tx * 4;
    float bx = b_ih[n + 0] + b_hh[n + 0];
    float by_ = b_ih[n + 1] + b_hh[n + 1];
    float bz = b_ih[n + 2] + b_hh[n + 2];
    float bw = b_ih[n + 3] + b_hh[n + 3];
#pragma unroll
    for (int i = 0; i < 4; i++) {
        int b = ty * 4 + i;
        float4 v = make_float4(acc[i][0] + bx, acc[i][1] + by_,
                               acc[i][2] + bz, acc[i][3] + bw);
        *(float4*)(g_xg + ((size_t)t * B_ + b) * G_ + n) = v;
    }
}

// ---------------- Phase B: persistent recurrence, TMA-bulk A ----------------
// Grid = 128 blocks, 256 threads (8 warps). Block bx owns 8 hidden units.
// Warp w owns K-cols {s*256 + w*32 + kk*16}. W_hi frags in 64 regs (once);
// W_lo resident in smem (64KB). A (=h image) arrives per stage via ONE
// cp.async.bulk of 64KB (already swizzled in global). Per step:
// acc[64][32] += h_hi@W_hi + h_hi@W_lo + h_lo@W_hi; partials merged in smem
// (aliasing the A buffers, which are dead by then).
static constexpr uint32_t OFF_A0  = 0;          // 64KB stage buf 0
static constexpr uint32_t OFF_A1  = 65536;      // 64KB stage buf 1
static constexpr uint32_t OFF_WLO = 131072;     // 64KB resident W_lo
static constexpr uint32_t OFF_MB  = 196608;     // 2 mbarriers
static constexpr uint32_t OFF_S   = 0;          // ssum aliases A bufs (dead)
static constexpr uint32_t SMEM_USED = OFF_MB + 16;
static constexpr uint32_t SMEM_REQ  = SMEM_USED + 1024;

__global__ __launch_bounds__(256, 1) void lstm_persistent(
    const int* __restrict__ seq_len, float* __restrict__ out)
{
    extern __shared__ char dsm_raw[];
    uint32_t raw = smem_to_u32(dsm_raw);
    uint32_t sbase = (raw + 1023u) & ~1023u;
    char* sm = dsm_raw + (sbase - raw);

    int tid = threadIdx.x;
    int wid = tid >> 5, lane = tid & 31;
    int bx = blockIdx.x;
    int j0 = bx * 8;

    // ldmatrix lane addressing
    int q8 = lane >> 3, r8 = lane & 7;
    uint32_t a_lrow = (uint32_t)(r8 + (q8 & 1) * 8);
    uint32_t a_kb   = (uint32_t)((q8 >> 1) * 16);
    uint32_t b_lrow = (uint32_t)(r8 + (q8 >> 1) * 8);
    uint32_t b_kb   = (uint32_t)((q8 & 1) * 16);

    if (tid == 0) {
        MBARRIER_INIT(sbase + OFF_MB, 1);
        MBARRIER_INIT(sbase + OFF_MB + 8, 1);
    }

    // ---- load W: hi staged into A-buf then ldsm'd to regs; lo resident smem ----
    uint32_t wr[4][2][4][2];   // [stage][kk][nt][2] W_hi fragments
    {
        int rr = tid >> 3;                    // 0..31 gate-row
        int cb = (tid & 7) * 8;               // 0..56
        int gn = (rr >> 3) * H_ + j0 + (rr & 7);
        const __nv_bfloat16* wrow = g_WW + (size_t)gn * 2048;
#pragma unroll
        for (int it = 0; it < 16; it++) {
            int col = it * 64 + cb;
            uint32_t soff = (uint32_t)((col >> 6) * 4096) +
                            SWZ((uint32_t)(rr * 128 + (col & 63) * 2));
            uint4 vh = *(const uint4*)(wrow + col);
            uint4 vl = *(const uint4*)(wrow + 1024 + col);
            *(uint4*)(sm + OFF_A0 + soff)  = vh;   // hi (temp)
            *(uint4*)(sm + OFF_WLO + soff) = vl;   // lo (resident)
        }
        __syncthreads();
#pragma unroll
        for (int s = 0; s < 4; s++)
#pragma unroll
            for (int kk = 0; kk < 2; kk++) {
                int scol = s * 256 + wid * 32 + kk * 16;
                uint32_t sub = (uint32_t)((scol >> 6) * 4096);
                uint32_t cin2 = (uint32_t)((scol & 63) * 2) + b_kb;
                ldsm_x4(wr[s][kk][0][0], wr[s][kk][0][1],
                        wr[s][kk][1][0], wr[s][kk][1][1],
                        sbase + OFF_A0 + sub + SWZ(b_lrow * 128 + cin2));
                ldsm_x4(wr[s][kk][2][0], wr[s][kk][2][1],
                        wr[s][kk][3][0], wr[s][kk][3][1],
                        sbase + OFF_A0 + sub + SWZ((b_lrow + 16) * 128 + cin2));
            }
        __syncthreads();
    }

    // per-warp A-ldsm constants
    uint32_t asub0 = (uint32_t)(((wid * 32) >> 6) * 16384);
    uint32_t acin0 = (uint32_t)(((wid * 32) & 63) * 2) + a_kb;
    uint32_t asub1 = (uint32_t)(((wid * 32 + 16) >> 6) * 16384);
    uint32_t acin1 = (uint32_t)(((wid * 32 + 16) & 63) * 2) + a_kb;

    // epilogue: 2 items per thread (b, u)
    int eb0 = tid >> 3;                  // 0..31
    int eb1 = eb0 + 32;                  // 32..63
    int eu = tid & 7;
    int ej = j0 + eu;
    int sl0 = seq_len[eb0], sl1 = seq_len[eb1];
    float c0 = 0.f, c1 = 0.f;
    // swizzled-global write offsets for h
    int hs = ej >> 8, hsub = (ej >> 6) & 3, hcin = ej & 63;
    uint32_t hbase = (uint32_t)((hs * 4 + hsub) * 16384);
    uint32_t hoff0 = hbase + SWZ((uint32_t)(eb0 * 128 + hcin * 2));
    uint32_t hoff0l = hbase + SWZ((uint32_t)((eb0 + 64) * 128 + hcin * 2));
    uint32_t hoff1 = hbase + SWZ((uint32_t)(eb1 * 128 + hcin * 2));
    uint32_t hoff1l = hbase + SWZ((uint32_t)((eb1 + 64) * 128 + hcin * 2));

    float* ssum = (float*)(sm + OFF_S);
    volatile int* flags = (volatile int*)g_flags;
    uint32_t done0 = 0, done1 = 0;

    __syncthreads();

#pragma unroll 1
    for (int t = 0; t < T_; t++) {
        const uint8_t* __restrict__ hin2 = g_hh2[t & 1];
        uint8_t* __restrict__ hout2 = g_hh2[(t + 1) & 1];

        // issue stages 0 and 1 (one bulk copy each)
        if (tid == 0) {
            MBARRIER_EXPECT_TX(sbase + OFF_MB, 65536);
            cp_bulk_g2s(sbase + OFF_A0, hin2, 65536, sbase + OFF_MB);
            MBARRIER_EXPECT_TX(sbase + OFF_MB + 8, 65536);
            cp_bulk_g2s(sbase + OFF_A1, hin2 + 65536, 65536, sbase + OFF_MB + 8);
        }

        // prefetch xg for epilogue
        float xr0[4], xr1[4];
        {
            const float* xa = g_xg + ((size_t)t * B_ + eb0) * G_ + ej;
            const float* xb = g_xg + ((size_t)t * B_ + eb1) * G_ + ej;
#pragma unroll
            for (int g4 = 0; g4 < 4; g4++) { xr0[g4] = xa[g4 * H_]; xr1[g4] = xb[g4 * H_]; }
        }

        float acc[4][4][4];
#pragma unroll
        for (int mt = 0; mt < 4; mt++)
#pragma unroll
            for (int nt = 0; nt < 4; nt++)
#pragma unroll
                for (int i = 0; i < 4; i++) acc[mt][nt][i] = 0.f;

#pragma unroll
        for (int s = 0; s < 4; s++) {
            uint32_t abuf = (s & 1) ? OFF_A1 : OFF_A0;
            if (s & 1) { MBARRIER_WAIT_PARITY(sbase + OFF_MB + 8, done1 & 1); done1++; }
            else       { MBARRIER_WAIT_PARITY(sbase + OFF_MB,     done0 & 1); done0++; }

#pragma unroll
            for (int kk = 0; kk < 2; kk++) {
                uint32_t atile = sbase + abuf + (kk ? asub1 : asub0);
                uint32_t cin2  = kk ? acin1 : acin0;
                int scol = s * 256 + wid * 32 + kk * 16;
                uint32_t wsub = (uint32_t)((scol >> 6) * 4096);
                uint32_t wcin2 = (uint32_t)((scol & 63) * 2) + b_kb;

                uint32_t ah[4][4];
#pragma unroll
                for (int mt = 0; mt < 4; mt++)
                    ldsm_x4(ah[mt][0], ah[mt][1], ah[mt][2], ah[mt][3],
                            atile + SWZ((mt * 16 + a_lrow) * 128 + cin2));
                uint32_t wl[4][2];
                ldsm_x4(wl[0][0], wl[0][1], wl[1][0], wl[1][1],
                        sbase + OFF_WLO + wsub + SWZ(b_lrow * 128 + wcin2));
                ldsm_x4(wl[2][0], wl[2][1], wl[3][0], wl[3][1],
                        sbase + OFF_WLO + wsub + SWZ((b_lrow + 16) * 128 + wcin2));
                // hi x W_hi
#pragma unroll
                for (int mt = 0; mt < 4; mt++)
#pragma unroll
                    for (int nt = 0; nt < 4; nt++)
                        hmma16816(acc[mt][nt], ah[mt][0], ah[mt][1], ah[mt][2], ah[mt][3],
                                  wr[s][kk][nt][0], wr[s][kk][nt][1]);
                // hi x W_lo
#pragma unroll
                for (int mt = 0; mt < 4; mt++)
#pragma unroll
                    for (int nt = 0; nt < 4; nt++)
                        hmma16816(acc[mt][nt], ah[mt][0], ah[mt][1], ah[mt][2], ah[mt][3],
                                  wl[nt][0], wl[nt][1]);
                // lo rows x W_hi
#pragma unroll
                for (int mt = 0; mt < 4; mt++)
                    ldsm_x4(ah[mt][0], ah[mt][1], ah[mt][2], ah[mt][3],
                            atile + SWZ((64 + mt * 16 + a_lrow) * 128 + cin2));
#pragma unroll
                for (int mt = 0; mt < 4; mt++)
#pragma unroll
                    for (int nt = 0; nt < 4; nt++)
                        hmma16816(acc[mt][nt], ah[mt][0], ah[mt][1], ah[mt][2], ah[mt][3],
                                  wr[s][kk][nt][0], wr[s][kk][nt][1]);
            }
            __syncthreads();   // all warps done with buf before refill
            if (s < 2 && tid == 0) {
                uint32_t mb = sbase + OFF_MB + (s & 1) * 8;
                MBARRIER_EXPECT_TX(mb, 65536);
                cp_bulk_g2s(sbase + abuf, hin2 + (s + 2) * 65536, 65536, mb);
            }
        }

        // ---- store pre-reduced partials (ssum aliases dead A bufs) ----
        {
            int r = lane >> 2, c4 = lane & 3;
            float* pp = ssum + wid * (64 * 34);
#pragma unroll
            for (int mt = 0; mt < 4; mt++)
#pragma unroll
                for (int nt = 0; nt < 4; nt++) {
                    int b1 = mt * 16 + r, n = nt * 8 + c4 * 2;
                    *(float2*)(pp + b1 * 34 + n) =
                        make_float2(acc[mt][nt][0], acc[mt][nt][1]);
                    *(float2*)(pp + (b1 + 8) * 34 + n) =
                        make_float2(acc[mt][nt][2], acc[mt][nt][3]);
                }
        }
        __syncthreads();

        // ---- epilogue: 2 items/thread ----
#pragma unroll
        for (int it = 0; it < 2; it++) {
            int b = it ? eb1 : eb0;
            float gate[4];
#pragma unroll
            for (int g4 = 0; g4 < 4; g4++) {
                int n = g4 * 8 + eu;
                float s0 = 0.f;
#pragma unroll
                for (int w = 0; w < 8; w++)
                    s0 += ssum[w * (64 * 34) + b * 34 + n];
                gate[g4] = s0 + (it ? xr1[g4] : xr0[g4]);
            }
            float si = sigf(gate[0]);
            float sf = sigf(gate[1]);
            float tg = tanh_fast(gate[2]);
            float so = sigf(gate[3]);
            float cn = fmaf(sf, it ? c1 : c0, si * tg);
            if (it) c1 = cn; else c0 = cn;
            float hn = so * tanh_fast(cn);
            __nv_bfloat16 hi = __float2bfloat16(hn);
            __nv_bfloat16 lo = __float2bfloat16(hn - __bfloat162float(hi));
            *(__nv_bfloat16*)(hout2 + (it ? hoff1 : hoff0)) = hi;
            *(__nv_bfloat16*)(hout2 + (it ? hoff1l : hoff0l)) = lo;
            out[((size_t)b * T_ + t) * H_ + ej] = (t < (it ? sl1 : sl0)) ? hn : 0.f;
        }

        // ---- grid barrier ----
        __threadfence();
        __syncthreads();
        if (tid == 0) flags[bx] = t + 1;
        if (tid < 128) {
            while (flags[tid] < t + 1) { }
        }
        __syncthreads();
        __threadfence();
    }
}

extern "C" void kernel_launch(void* const* d_in, const int* in_sizes, int n_in,
                              void* d_out, int out_size)
{
    const float* feature = (const float*)d_in[0];
    const float* W_ih    = (const float*)d_in[1];
    const float* W_hh    = (const float*)d_in[2];
    const float* b_ih    = (const float*)d_in[3];
    const float* b_hh    = (const float*)d_in[4];
    const int*   seq_len = (const int*)d_in[5];
    float* out = (float*)d_out;

    cudaFuncSetAttribute(lstm_persistent, cudaFuncAttributeMaxDynamicSharedMemorySize,
                         SMEM_REQ);

    init_state_kernel<<<(131072 + 255) / 256, 256>>>();
    build_WW_kernel<<<(G_ * H_ + 255) / 256, 256>>>(W_hh);
    gemm_xg_kernel<<<dim3(G_ / 64, T_), 256>>>(feature, W_ih, b_ih, b_hh);
    lstm_persistent<<<128, 256, SMEM_REQ>>>(seq_len, out);
}

// round 11
// speedup vs baseline: 1.3728x; 1.3250x over previous
#include <cuda_runtime.h>
#include <cuda_bf16.h>
#include <math.h>
#include <stdint.h>

#define B_ 64
#define T_ 512
#define D_ 1024
#define H_ 1024
#define G_ 4096

// ---------------- device scratch (allocation-free rule) ----------------
__device__ float g_xg[(size_t)T_ * B_ * G_];            // [T][B][4H] pre-activations
// h ping-pong, stored as the SW128-swizzled SMEM image:
// [pp][stage s][subtile][128 rows][128B]; rows 0-63 h_hi, 64-127 h_lo
__device__ __align__(128) uint8_t g_hh2[2][4 * 4 * 128 * 128];
__device__ __nv_bfloat16 g_WW[(size_t)G_ * 2 * H_];     // [4096][2048]: 0-1023 W_hi, 1024-2047 W_lo
__device__ unsigned g_prod[4];                          // per-group producer counters
__device__ unsigned g_cons;                             // consumption counter

#define SWZ(off) ((off) ^ (((off) >> 3) & 0x70))

__device__ __forceinline__ uint32_t smem_to_u32(const void* p) {
    uint32_t a;
    asm("{ .reg .u64 t; cvta.to.shared.u64 t, %1; cvt.u32.u64 %0, t; }" : "=r"(a) : "l"(p));
    return a;
}

__device__ __forceinline__ void ldsm_x4(uint32_t& r0, uint32_t& r1, uint32_t& r2,
                                        uint32_t& r3, uint32_t addr) {
    asm volatile("ldmatrix.sync.aligned.m8n8.x4.shared.b16 {%0,%1,%2,%3}, [%4];"
                 : "=r"(r0), "=r"(r1), "=r"(r2), "=r"(r3) : "r"(addr));
}

__device__ __forceinline__ void hmma16816(float* d, uint32_t a0, uint32_t a1,
                                          uint32_t a2, uint32_t a3,
                                          uint32_t b0, uint32_t b1) {
    asm volatile(
        "mma.sync.aligned.m16n8k16.row.col.f32.bf16.bf16.f32 "
        "{%0,%1,%2,%3}, {%4,%5,%6,%7}, {%8,%9}, {%0,%1,%2,%3};"
        : "+f"(d[0]), "+f"(d[1]), "+f"(d[2]), "+f"(d[3])
        : "r"(a0), "r"(a1), "r"(a2), "r"(a3), "r"(b0), "r"(b1));
}

// 1D bulk async copy global -> shared::cta with mbarrier completion (sm_90 PTX)
__device__ __forceinline__ void cp_bulk_g2s(uint32_t dst, const void* src,
                                            uint32_t bytes, uint32_t mbar) {
    asm volatile(
        "cp.async.bulk.shared::cta.global.mbarrier::complete_tx::bytes [%0], [%1], %2, [%3];"
        :: "r"(dst), "l"(src), "r"(bytes), "r"(mbar) : "memory");
}
#define MBARRIER_INIT(addr, cnt) \
    asm volatile("mbarrier.init.shared.b64 [%0], %1;" :: "r"((uint32_t)(addr)), "r"((uint32_t)(cnt)) : "memory")
#define MBARRIER_EXPECT_TX(addr, bytes) \
    asm volatile("mbarrier.arrive.expect_tx.shared.b64 _, [%0], %1;" \
        :: "r"((uint32_t)(addr)), "r"((uint32_t)(bytes)) : "memory")
#define MBARRIER_WAIT_PARITY(mbar_smem_addr, phase_parity) do { \
    uint32_t _mbar = (uint32_t)(mbar_smem_addr); \
    uint32_t _parity = (uint32_t)(phase_parity); \
    uint32_t _done; \
    asm volatile( \
        "{\n\t.reg .pred p;\n\t" \
        "mbarrier.try_wait.parity.acquire.cta.shared::cta.b64 p, [%1], %2;\n\t" \
        "selp.b32 %0, 1, 0, p;\n\t}" \
        : "=r"(_done) : "r"(_mbar), "r"(_parity) : "memory"); \
    if (!_done) { \
        asm volatile( \
            "{\n\t.reg .pred P1;\n\t" \
            "WAIT_LOOP_%=:\n\t" \
            "mbarrier.try_wait.parity.acquire.cta.shared::cta.b64 P1, [%0], %1, 0x989680;\n\t" \
            "@P1 bra.uni WAIT_DONE_%=;\n\t" \
            "bra.uni WAIT_LOOP_%=;\n\t" \
            "WAIT_DONE_%=:\n\t}" \
            :: "r"(_mbar), "r"(_parity) : "memory"); \
    } \
} while(0)

__device__ __forceinline__ float sigf(float x) {
    return __fdividef(1.f, 1.f + __expf(-x));
}
__device__ __forceinline__ float tanh_fast(float x) {
    x = fminf(fmaxf(x, -15.f), 15.f);
    float e = __expf(2.f * x);
    return __fdividef(e - 1.f, e + 1.f);
}

// ---------------- init kernels ----------------
__global__ void init_state_kernel() {
    int i = blockIdx.x * blockDim.x + threadIdx.x;
    // zero both h ping-pong images: 2*256KB = 131072 u32 words
    if (i < 131072) ((uint32_t*)g_hh2)[i] = 0u;
    if (i < 4) g_prod[i] = 0u;
    if (i == 4) g_cons = 0u;
}

__global__ void build_WW_kernel(const float* __restrict__ W_hh) {
    int i = blockIdx.x * blockDim.x + threadIdx.x;
    if (i < G_ * H_) {
        int row = i >> 10, col = i & 1023;
        float w = W_hh[i];
        __nv_bfloat16 hi = __float2bfloat16(w);
        __nv_bfloat16 lo = __float2bfloat16(w - __bfloat162float(hi));
        g_WW[(size_t)row * 2048 + col] = hi;
        g_WW[(size_t)row * 2048 + 1024 + col] = lo;
    }
}

// ---------------- Phase A: x_gates GEMM (fp32, proven) ----------------
__global__ __launch_bounds__(256) void gemm_xg_kernel(
    const float* __restrict__ feature, const float* __restrict__ W_ih,
    const float* __restrict__ b_ih, const float* __restrict__ b_hh)
{
    __shared__ __align__(16) float As[16][68];
    __shared__ __align__(16) float Bs[16][68];
    int tid = threadIdx.x;
    int tx = tid & 15, ty = tid >> 4;
    int n0 = blockIdx.x * 64;
    int t  = blockIdx.y;
    int lr = tid >> 2;
    int lk = (tid & 3) * 4;

    const float* fptr = feature + ((size_t)lr * T_ + t) * D_ + lk;
    const float* wptr = W_ih + (size_t)(n0 + lr) * D_ + lk;

    float acc[4][4] = {};
    for (int k0 = 0; k0 < D_; k0 += 16) {
        float4 av = *(const float4*)(fptr + k0);
        float4 bv = *(const float4*)(wptr + k0);
        __syncthreads();
        As[lk + 0][lr] = av.x; As[lk + 1][lr] = av.y;
        As[lk + 2][lr] = av.z; As[lk + 3][lr] = av.w;
        Bs[lk + 0][lr] = bv.x; Bs[lk + 1][lr] = bv.y;
        Bs[lk + 2][lr] = bv.z; Bs[lk + 3][lr] = bv.w;
        __syncthreads();
#pragma unroll
        for (int k = 0; k < 16; k++) {
            float4 a4 = *(const float4*)&As[k][ty * 4];
            float4 b4 = *(const float4*)&Bs[k][tx * 4];
            acc[0][0] = fmaf(a4.x, b4.x, acc[0][0]);
            acc[0][1] = fmaf(a4.x, b4.y, acc[0][1]);
            acc[0][2] = fmaf(a4.x, b4.z, acc[0][2]);
            acc[0][3] = fmaf(a4.x, b4.w, acc[0][3]);
            acc[1][0] = fmaf(a4.y, b4.x, acc[1][0]);
            acc[1][1] = fmaf(a4.y, b4.y, acc[1][1]);
            acc[1][2] = fmaf(a4.y, b4.z, acc[1][2]);
            acc[1][3] = fmaf(a4.y, b4.w, acc[1][3]);
            acc[2][0] = fmaf(a4.z, b4.x, acc[2][0]);
            acc[2][1] = fmaf(a4.z, b4.y, acc[2][1]);
            acc[2][2] = fmaf(a4.z, b4.z, acc[2][2]);
            acc[2][3] = fmaf(a4.z, b4.w, acc[2][3]);
            acc[3][0] = fmaf(a4.w, b4.x, acc[3][0]);
            acc[3][1] = fmaf(a4.w, b4.y, acc[3][1]);
            acc[3][2] = fmaf(a4.w, b4.z, acc[3][2]);
            acc[3][3] = fmaf(a4.w, b4.w, acc[3][3]);
        }
    }
    int n = n0 + tx * 4;
    float bx = b_ih[n + 0] + b_hh[n + 0];
    float by_ = b_ih[n + 1] + b_hh[n + 1];
    float bz = b_ih[n + 2] + b_hh[n + 2];
    float bw = b_ih[n + 3] + b_hh[n + 3];
#pragma unroll
    for (int i = 0; i < 4; i++) {
        int b = ty * 4 + i;
        float4 v = make_float4(acc[i][0] + bx, acc[i][1] + by_,
                               acc[i][2] + bz, acc[i][3] + bw);
        *(float4*)(g_xg + ((size_t)t * B_ + b) * G_ + n) = v;
    }
}

// ---------------- Phase B: persistent recurrence, group-synced pipeline ------
// Grid = 128 blocks, 256 threads (8 warps). Block bx owns 8 hidden units;
// its h outputs all fall in stage-group g = bx>>5. Stages processed in
// rotated order (g+1..g+4)&3 so the last dependency is the block's own group.
// Sync: g_prod[s] >= 32*t gates the stage-s bulk copy of step t (tid0 poll);
// g_cons >= 128*t gates the epilogue h overwrite. No full grid barrier.
static constexpr uint32_t OFF_A0  = 0;          // 64KB stage buf 0
static constexpr uint32_t OFF_A1  = 65536;      // 64KB stage buf 1
static constexpr uint32_t OFF_WLO = 131072;     // 64KB resident W_lo
static constexpr uint32_t OFF_MB  = 196608;     // 2 mbarriers
static constexpr uint32_t OFF_S   = 0;          // ssum aliases A bufs (dead)
static constexpr uint32_t SMEM_USED = OFF_MB + 16;
static constexpr uint32_t SMEM_REQ  = SMEM_USED + 1024;

__global__ __launch_bounds__(256, 1) void lstm_persistent(
    const int* __restrict__ seq_len, float* __restrict__ out)
{
    extern __shared__ char dsm_raw[];
    uint32_t raw = smem_to_u32(dsm_raw);
    uint32_t sbase = (raw + 1023u) & ~1023u;
    char* sm = dsm_raw + (sbase - raw);

    int tid = threadIdx.x;
    int wid = tid >> 5, lane = tid & 31;
    int bx = blockIdx.x;
    int j0 = bx * 8;
    int grp = bx >> 5;                 // my producer group

    // ldmatrix lane addressing
    int q8 = lane >> 3, r8 = lane & 7;
    uint32_t a_lrow = (uint32_t)(r8 + (q8 & 1) * 8);
    uint32_t a_kb   = (uint32_t)((q8 >> 1) * 16);
    uint32_t b_lrow = (uint32_t)(r8 + (q8 >> 1) * 8);
    uint32_t b_kb   = (uint32_t)((q8 & 1) * 16);

    if (tid == 0) {
        MBARRIER_INIT(sbase + OFF_MB, 1);
        MBARRIER_INIT(sbase + OFF_MB + 8, 1);
    }

    // rotated stage order: slot i -> stage (grp+1+i)&3 (runtime, load-time only)
    int sg[4];
#pragma unroll
    for (int i = 0; i < 4; i++) sg[i] = (grp + 1 + i) & 3;

    // ---- load W: hi staged into A-buf then ldsm'd to regs; lo resident smem ----
    uint32_t wr[4][2][4][2];   // [slot][kk][nt][2] W_hi fragments (rotated)
    {
        int rr = tid >> 3;                    // 0..31 gate-row
        int cb = (tid & 7) * 8;               // 0..56
        int gn = (rr >> 3) * H_ + j0 + (rr & 7);
        const __nv_bfloat16* wrow = g_WW + (size_t)gn * 2048;
#pragma unroll
        for (int it = 0; it < 16; it++) {
            int col = it * 64 + cb;
            uint32_t soff = (uint32_t)((col >> 6) * 4096) +
                            SWZ((uint32_t)(rr * 128 + (col & 63) * 2));
            uint4 vh = *(const uint4*)(wrow + col);
            uint4 vl = *(const uint4*)(wrow + 1024 + col);
            *(uint4*)(sm + OFF_A0 + soff)  = vh;   // hi (temp)
            *(uint4*)(sm + OFF_WLO + soff) = vl;   // lo (resident)
        }
        __syncthreads();
#pragma unroll
        for (int i = 0; i < 4; i++)
#pragma unroll
            for (int kk = 0; kk < 2; kk++) {
                int scol = sg[i] * 256 + wid * 32 + kk * 16;
                uint32_t sub = (uint32_t)((scol >> 6) * 4096);
                uint32_t cin2 = (uint32_t)((scol & 63) * 2) + b_kb;
                ldsm_x4(wr[i][kk][0][0], wr[i][kk][0][1],
                        wr[i][kk][1][0], wr[i][kk][1][1],
                        sbase + OFF_A0 + sub + SWZ(b_lrow * 128 + cin2));
                ldsm_x4(wr[i][kk][2][0], wr[i][kk][2][1],
                        wr[i][kk][3][0], wr[i][kk][3][1],
                        sbase + OFF_A0 + sub + SWZ((b_lrow + 16) * 128 + cin2));
            }
        __syncthreads();
    }

    // per-warp A-ldsm constants
    uint32_t asub0 = (uint32_t)(((wid * 32) >> 6) * 16384);
    uint32_t acin0 = (uint32_t)(((wid * 32) & 63) * 2) + a_kb;
    uint32_t asub1 = (uint32_t)(((wid * 32 + 16) >> 6) * 16384);
    uint32_t acin1 = (uint32_t)(((wid * 32 + 16) & 63) * 2) + a_kb;

    // epilogue: 2 items per thread (b, u)
    int eb0 = tid >> 3;                  // 0..31
    int eb1 = eb0 + 32;                  // 32..63
    int eu = tid & 7;
    int ej = j0 + eu;
    int sl0 = seq_len[eb0], sl1 = seq_len[eb1];
    float c0 = 0.f, c1 = 0.f;
    // swizzled-global write offsets for h
    int hs = ej >> 8, hsub = (ej >> 6) & 3, hcin = ej & 63;
    uint32_t hbase = (uint32_t)((hs * 4 + hsub) * 16384);
    uint32_t hoff0 = hbase + SWZ((uint32_t)(eb0 * 128 + hcin * 2));
    uint32_t hoff0l = hbase + SWZ((uint32_t)((eb0 + 64) * 128 + hcin * 2));
    uint32_t hoff1 = hbase + SWZ((uint32_t)(eb1 * 128 + hcin * 2));
    uint32_t hoff1l = hbase + SWZ((uint32_t)((eb1 + 64) * 128 + hcin * 2));

    float* ssum = (float*)(sm + OFF_S);
    volatile unsigned* prod = (volatile unsigned*)g_prod;
    volatile unsigned* cons = (volatile unsigned*)&g_cons;
    uint32_t done0 = 0, done1 = 0;

    __syncthreads();

#pragma unroll 1
    for (int t = 0; t < T_; t++) {
        const uint8_t* __restrict__ hin2 = g_hh2[t & 1];
        uint8_t* __restrict__ hout2 = g_hh2[(t + 1) & 1];
        unsigned needp = 32u * (unsigned)t;

        // issue slots 0 and 1 (one bulk copy each), gated by producer counters
        if (tid == 0) {
            while (prod[sg[0]] < needp) { }
            MBARRIER_EXPECT_TX(sbase + OFF_MB, 65536);
            cp_bulk_g2s(sbase + OFF_A0, hin2 + sg[0] * 65536, 65536, sbase + OFF_MB);
            while (prod[sg[1]] < needp) { }
            MBARRIER_EXPECT_TX(sbase + OFF_MB + 8, 65536);
            cp_bulk_g2s(sbase + OFF_A1, hin2 + sg[1] * 65536, 65536, sbase + OFF_MB + 8);
        }

        // prefetch xg for epilogue
        float xr0[4], xr1[4];
        {
            const float* xa = g_xg + ((size_t)t * B_ + eb0) * G_ + ej;
            const float* xb = g_xg + ((size_t)t * B_ + eb1) * G_ + ej;
#pragma unroll
            for (int g4 = 0; g4 < 4; g4++) { xr0[g4] = xa[g4 * H_]; xr1[g4] = xb[g4 * H_]; }
        }

        float acc[4][4][4];
#pragma unroll
        for (int mt = 0; mt < 4; mt++)
#pragma unroll
            for (int nt = 0; nt < 4; nt++)
#pragma unroll
                for (int i = 0; i < 4; i++) acc[mt][nt][i] = 0.f;

#pragma unroll
        for (int i = 0; i < 4; i++) {
            uint32_t abuf = (i & 1) ? OFF_A1 : OFF_A0;
            if (i & 1) { MBARRIER_WAIT_PARITY(sbase + OFF_MB + 8, done1 & 1); done1++; }
            else       { MBARRIER_WAIT_PARITY(sbase + OFF_MB,     done0 & 1); done0++; }
            if (i == 3 && tid == 0) atomicAdd(&g_cons, 1u);   // h[t] fully consumed

            int srt = sg[i];
#pragma unroll
            for (int kk = 0; kk < 2; kk++) {
                uint32_t atile = sbase + abuf + (kk ? asub1 : asub0);
                uint32_t cin2  = kk ? acin1 : acin0;
                int scol = srt * 256 + wid * 32 + kk * 16;
                uint32_t wsub = (uint32_t)((scol >> 6) * 4096);
                uint32_t wcin2 = (uint32_t)((scol & 63) * 2) + b_kb;

                uint32_t ah[4][4];
#pragma unroll
                for (int mt = 0; mt < 4; mt++)
                    ldsm_x4(ah[mt][0], ah[mt][1], ah[mt][2], ah[mt][3],
                            atile + SWZ((mt * 16 + a_lrow) * 128 + cin2));
                uint32_t wl[4][2];
                ldsm_x4(wl[0][0], wl[0][1], wl[1][0], wl[1][1],
                        sbase + OFF_WLO + wsub + SWZ(b_lrow * 128 + wcin2));
                ldsm_x4(wl[2][0], wl[2][1], wl[3][0], wl[3][1],
                        sbase + OFF_WLO + wsub + SWZ((b_lrow + 16) * 128 + wcin2));
                // hi x W_hi
#pragma unroll
                for (int mt = 0; mt < 4; mt++)
#pragma unroll
                    for (int nt = 0; nt < 4; nt++)
                        hmma16816(acc[mt][nt], ah[mt][0], ah[mt][1], ah[mt][2], ah[mt][3],
                                  wr[i][kk][nt][0], wr[i][kk][nt][1]);
                // hi x W_lo
#pragma unroll
                for (int mt = 0; mt < 4; mt++)
#pragma unroll
                    for (int nt = 0; nt < 4; nt++)
                        hmma16816(acc[mt][nt], ah[mt][0], ah[mt][1], ah[mt][2], ah[mt][3],
                                  wl[nt][0], wl[nt][1]);
                // lo rows x W_hi
#pragma unroll
                for (int mt = 0; mt < 4; mt++)
                    ldsm_x4(ah[mt][0], ah[mt][1], ah[mt][2], ah[mt][3],
                            atile + SWZ((64 + mt * 16 + a_lrow) * 128 + cin2));
#pragma unroll
                for (int mt = 0; mt < 4; mt++)
#pragma unroll
                    for (int nt = 0; nt < 4; nt++)
                        hmma16816(acc[mt][nt], ah[mt][0], ah[mt][1], ah[mt][2], ah[mt][3],
                                  wr[i][kk][nt][0], wr[i][kk][nt][1]);
            }
            __syncthreads();   // all warps done with buf before refill
            if (i < 2 && tid == 0) {
                while (prod[sg[i + 2]] < needp) { }
                uint32_t mb = sbase + OFF_MB + (i & 1) * 8;
                MBARRIER_EXPECT_TX(mb, 65536);
                cp_bulk_g2s(sbase + abuf, hin2 + sg[i + 2] * 65536, 65536, mb);
            }
        }

        // ---- store pre-reduced partials (ssum aliases dead A bufs) ----
        {
            int r = lane >> 2, c4 = lane & 3;
            float* pp = ssum + wid * (64 * 34);
#pragma unroll
            for (int mt = 0; mt < 4; mt++)
#pragma unroll
                for (int nt = 0; nt < 4; nt++) {
                    int b1 = mt * 16 + r, n = nt * 8 + c4 * 2;
                    *(float2*)(pp + b1 * 34 + n) =
                        make_float2(acc[mt][nt][0], acc[mt][nt][1]);
                    *(float2*)(pp + (b1 + 8) * 34 + n) =
                        make_float2(acc[mt][nt][2], acc[mt][nt][3]);
                }
        }
        __syncthreads();

        // gate: all blocks must have consumed h[t-1] before we overwrite its image
        if (tid == 0) {
            unsigned needc = 128u * (unsigned)t;
            while (*cons < needc) { }
        }
        __syncthreads();

        // ---- epilogue: 2 items/thread ----
#pragma unroll
        for (int it = 0; it < 2; it++) {
            int b = it ? eb1 : eb0;
            float gate[4];
#pragma unroll
            for (int g4 = 0; g4 < 4; g4++) {
                int n = g4 * 8 + eu;
                float s0 = 0.f;
#pragma unroll
                for (int w = 0; w < 8; w++)
                    s0 += ssum[w * (64 * 34) + b * 34 + n];
                gate[g4] = s0 + (it ? xr1[g4] : xr0[g4]);
            }
            float si = sigf(gate[0]);
            float sf = sigf(gate[1]);
            float tg = tanh_fast(gate[2]);
            float so = sigf(gate[3]);
            float cn = fmaf(sf, it ? c1 : c0, si * tg);
            if (it) c1 = cn; else c0 = cn;
            float hn = so * tanh_fast(cn);
            __nv_bfloat16 hi = __float2bfloat16(hn);
            __nv_bfloat16 lo = __float2bfloat16(hn - __bfloat162float(hi));
            *(__nv_bfloat16*)(hout2 + (it ? hoff1 : hoff0)) = hi;
            *(__nv_bfloat16*)(hout2 + (it ? hoff1l : hoff0l)) = lo;
            out[((size_t)b * T_ + t) * H_ + ej] = (t < (it ? sl1 : sl0)) ? hn : 0.f;
        }

        // ---- publish h[t+1] for my group ----
        __threadfence();
        __syncthreads();
        if (tid == 0) atomicAdd(&g_prod[grp], 1u);
    }
}

extern "C" void kernel_launch(void* const* d_in, const int* in_sizes, int n_in,
                              void* d_out, int out_size)
{
    const float* feature = (const float*)d_in[0];
    const float* W_ih    = (const float*)d_in[1];
    const float* W_hh    = (const float*)d_in[2];
    const float* b_ih    = (const float*)d_in[3];
    const float* b_hh    = (const float*)d_in[4];
    const int*   seq_len = (const int*)d_in[5];
    float* out = (float*)d_out;

    cudaFuncSetAttribute(lstm_persistent, cudaFuncAttributeMaxDynamicSharedMemorySize,
                         SMEM_REQ);

    init_state_kernel<<<(131072 + 255) / 256, 256>>>();
    build_WW_kernel<<<(G_ * H_ + 255) / 256, 256>>>(W_hh);
    gemm_xg_kernel<<<dim3(G_ / 64, T_), 256>>>(feature, W_ih, b_ih, b_hh);
    lstm_persistent<<<128, 256, SMEM_REQ>>>(seq_len, out);
}

// round 12
// speedup vs baseline: 2.5317x; 1.8442x over previous
#include <cuda_runtime.h>
#include <cuda_bf16.h>
#include <math.h>
#include <stdint.h>

#define B_ 64
#define T_ 512
#define D_ 1024
#define H_ 1024
#define G_ 4096

// ---------------- device scratch (allocation-free rule) ----------------
__device__ float g_xg[(size_t)T_ * B_ * G_];            // [T][B][4H] pre-activations
// h ping-pong, stored as the SW128-swizzled SMEM image:
// [pp][stage s][subtile][128 rows][128B]; rows 0-63 h_hi, 64-127 h_lo
__device__ __align__(128) uint8_t g_hh2[2][4 * 4 * 128 * 128];
__device__ __nv_bfloat16 g_WW[(size_t)G_ * 2 * H_];     // [4096][2048]: 0-1023 W_hi, 1024-2047 W_lo
__device__ __nv_bfloat16 g_Wih2[(size_t)G_ * 2 * D_];   // W_ih hi|lo, same layout
__device__ __nv_bfloat16 g_fh[(size_t)T_ * B_ * D_];    // feature hi, rows m = t*64+b
__device__ __nv_bfloat16 g_fl[(size_t)T_ * B_ * D_];    // feature lo
__device__ unsigned g_prod[4];                          // per-group producer counters
__device__ unsigned g_cons;                             // consumption counter

#define SWZ(off) ((off) ^ (((off) >> 3) & 0x70))

__device__ __forceinline__ uint32_t smem_to_u32(const void* p) {
    uint32_t a;
    asm("{ .reg .u64 t; cvta.to.shared.u64 t, %1; cvt.u32.u64 %0, t; }" : "=r"(a) : "l"(p));
    return a;
}

__device__ __forceinline__ void ldsm_x4(uint32_t& r0, uint32_t& r1, uint32_t& r2,
                                        uint32_t& r3, uint32_t addr) {
    asm volatile("ldmatrix.sync.aligned.m8n8.x4.shared.b16 {%0,%1,%2,%3}, [%4];"
                 : "=r"(r0), "=r"(r1), "=r"(r2), "=r"(r3) : "r"(addr));
}

__device__ __forceinline__ void hmma16816(float* d, uint32_t a0, uint32_t a1,
                                          uint32_t a2, uint32_t a3,
                                          uint32_t b0, uint32_t b1) {
    asm volatile(
        "mma.sync.aligned.m16n8k16.row.col.f32.bf16.bf16.f32 "
        "{%0,%1,%2,%3}, {%4,%5,%6,%7}, {%8,%9}, {%0,%1,%2,%3};"
        : "+f"(d[0]), "+f"(d[1]), "+f"(d[2]), "+f"(d[3])
        : "r"(a0), "r"(a1), "r"(a2), "r"(a3), "r"(b0), "r"(b1));
}

__device__ __forceinline__ void cp_async16(uint32_t dst, const void* src) {
    asm volatile("cp.async.cg.shared.global [%0], [%1], 16;"
                 :: "r"(dst), "l"(src) : "memory");
}
#define CP_COMMIT() asm volatile("cp.async.commit_group;" ::: "memory")
#define CP_WAIT(N)  asm volatile("cp.async.wait_group %0;" :: "n"(N) : "memory")

// 1D bulk async copy global -> shared::cta with mbarrier completion (sm_90 PTX)
__device__ __forceinline__ void cp_bulk_g2s(uint32_t dst, const void* src,
                                            uint32_t bytes, uint32_t mbar) {
    asm volatile(
        "cp.async.bulk.shared::cta.global.mbarrier::complete_tx::bytes [%0], [%1], %2, [%3];"
        :: "r"(dst), "l"(src), "r"(bytes), "r"(mbar) : "memory");
}
#define MBARRIER_INIT(addr, cnt) \
    asm volatile("mbarrier.init.shared.b64 [%0], %1;" :: "r"((uint32_t)(addr)), "r"((uint32_t)(cnt)) : "memory")
#define MBARRIER_EXPECT_TX(addr, bytes) \
    asm volatile("mbarrier.arrive.expect_tx.shared.b64 _, [%0], %1;" \
        :: "r"((uint32_t)(addr)), "r"((uint32_t)(bytes)) : "memory")
#define MBARRIER_WAIT_PARITY(mbar_smem_addr, phase_parity) do { \
    uint32_t _mbar = (uint32_t)(mbar_smem_addr); \
    uint32_t _parity = (uint32_t)(phase_parity); \
    uint32_t _done; \
    asm volatile( \
        "{\n\t.reg .pred p;\n\t" \
        "mbarrier.try_wait.parity.acquire.cta.shared::cta.b64 p, [%1], %2;\n\t" \
        "selp.b32 %0, 1, 0, p;\n\t}" \
        : "=r"(_done) : "r"(_mbar), "r"(_parity) : "memory"); \
    if (!_done) { \
        asm volatile( \
            "{\n\t.reg .pred P1;\n\t" \
            "WAIT_LOOP_%=:\n\t" \
            "mbarrier.try_wait.parity.acquire.cta.shared::cta.b64 P1, [%0], %1, 0x989680;\n\t" \
            "@P1 bra.uni WAIT_DONE_%=;\n\t" \
            "bra.uni WAIT_LOOP_%=;\n\t" \
            "WAIT_DONE_%=:\n\t}" \
            :: "r"(_mbar), "r"(_parity) : "memory"); \
    } \
} while(0)

__device__ __forceinline__ float sigf(float x) {
    return __fdividef(1.f, 1.f + __expf(-x));
}
__device__ __forceinline__ float tanh_fast(float x) {
    x = fminf(fmaxf(x, -15.f), 15.f);
    float e = __expf(2.f * x);
    return __fdividef(e - 1.f, e + 1.f);
}

// ---------------- init / prep kernels ----------------
__global__ void init_state_kernel() {
    int i = blockIdx.x * blockDim.x + threadIdx.x;
    if (i < 131072) ((uint32_t*)g_hh2)[i] = 0u;
    if (i < 4) g_prod[i] = 0u;
    if (i == 4) g_cons = 0u;
}

__global__ void build_WW_kernel(const float* __restrict__ W_hh) {
    int i = blockIdx.x * blockDim.x + threadIdx.x;
    if (i < G_ * H_) {
        int row = i >> 10, col = i & 1023;
        float w = W_hh[i];
        __nv_bfloat16 hi = __float2bfloat16(w);
        __nv_bfloat16 lo = __float2bfloat16(w - __bfloat162float(hi));
        g_WW[(size_t)row * 2048 + col] = hi;
        g_WW[(size_t)row * 2048 + 1024 + col] = lo;
    }
}

__global__ void build_Wih2_kernel(const float* __restrict__ W_ih) {
    int i = blockIdx.x * blockDim.x + threadIdx.x;
    if (i < G_ * D_) {
        int row = i >> 10, col = i & 1023;
        float w = W_ih[i];
        __nv_bfloat16 hi = __float2bfloat16(w);
        __nv_bfloat16 lo = __float2bfloat16(w - __bfloat162float(hi));
        g_Wih2[(size_t)row * 2048 + col] = hi;
        g_Wih2[(size_t)row * 2048 + 1024 + col] = lo;
    }
}

// feature [b][t][d] -> f_hi/f_lo rows m = t*64+b
__global__ void build_fA_kernel(const float* __restrict__ feature) {
    size_t i = (size_t)blockIdx.x * blockDim.x + threadIdx.x;
    if (i < (size_t)T_ * B_ * D_) {
        int k = (int)(i & 1023);
        int m = (int)(i >> 10);
        int tt = m >> 6, b = m & 63;
        float v = feature[((size_t)b * T_ + tt) * D_ + k];
        __nv_bfloat16 hi = __float2bfloat16(v);
        g_fh[i] = hi;
        g_fl[i] = __float2bfloat16(v - __bfloat162float(hi));
    }
}

// ---------------- Phase A: x_gates GEMM via HMMA (hi/lo 3-pass) ----------------
// grid (256 m-blocks, 32 n-blocks) x 256 thr. Tile 128m x 128n, K chunk 64,
// cp.async double-buffered. xg row m = t*64+b -> direct [m][n] store + bias.
static constexpr uint32_t XS_AH = 0;        // 16KB per region
static constexpr uint32_t XS_AL = 16384;
static constexpr uint32_t XS_BH = 32768;
static constexpr uint32_t XS_BL = 49152;
static constexpr uint32_t XS_STAGE = 65536;
static constexpr uint32_t XS_REQ = 2 * XS_STAGE + 1024;

__global__ __launch_bounds__(256, 1) void gemm_xg_tc(
    const float* __restrict__ b_ih, const float* __restrict__ b_hh)
{
    extern __shared__ char dsm_raw[];
    uint32_t raw = smem_to_u32(dsm_raw);
    uint32_t sbase = (raw + 1023u) & ~1023u;
    char* sm = dsm_raw + (sbase - raw);

    int tid = threadIdx.x;
    int wid = tid >> 5, lane = tid & 31;
    int m0 = blockIdx.x * 128;
    int n0 = blockIdx.y * 128;
    int wm = wid >> 1, wn = wid & 1;        // warp: 32 m-rows, 64 n-cols

    // ldmatrix lane addressing (proven constants)
    int q8 = lane >> 3, r8 = lane & 7;
    uint32_t a_lrow = (uint32_t)(r8 + (q8 & 1) * 8);
    uint32_t a_kb   = (uint32_t)((q8 >> 1) * 16);
    uint32_t b_lrow = (uint32_t)(r8 + (q8 >> 1) * 8);
    uint32_t b_kb   = (uint32_t)((q8 & 1) * 16);

    // staging indices: row 0..31, colB element 0..56
    int srow = tid >> 3;
    int colB = (tid & 7) * 8;
    uint32_t sdst = SWZ((uint32_t)(srow * 128 + colB * 2));  // same for each +32-row iter? no: row varies
    (void)sdst;

    // bias for this thread's 16 columns
    int r4 = lane >> 2, c4 = lane & 3;
    float2 bias2[8];
#pragma unroll
    for (int nt = 0; nt < 8; nt++) {
        int n = n0 + wn * 64 + nt * 8 + c4 * 2;
        bias2[nt] = make_float2(b_ih[n] + b_hh[n], b_ih[n + 1] + b_hh[n + 1]);
    }

    float acc[2][8][4];
#pragma unroll
    for (int mt = 0; mt < 2; mt++)
#pragma unroll
        for (int nt = 0; nt < 8; nt++)
#pragma unroll
            for (int i = 0; i < 4; i++) acc[mt][nt][i] = 0.f;

    // issue chunk 0
    {
        int kc = 0;
#pragma unroll
        for (int i = 0; i < 4; i++) {
            int r = srow + 32 * i;
            uint32_t d = SWZ((uint32_t)(r * 128 + colB * 2));
            cp_async16(sbase + XS_AH + d, g_fh + (size_t)(m0 + r) * 1024 + kc + colB);
            cp_async16(sbase + XS_AL + d, g_fl + (size_t)(m0 + r) * 1024 + kc + colB);
            cp_async16(sbase + XS_BH + d, g_Wih2 + (size_t)(n0 + r) * 2048 + kc + colB);
            cp_async16(sbase + XS_BL + d, g_Wih2 + (size_t)(n0 + r) * 2048 + 1024 + kc + colB);
        }
        CP_COMMIT();
    }

#pragma unroll 1
    for (int c = 0; c < 16; c++) {
        uint32_t sb = sbase + (c & 1) * XS_STAGE;
        CP_WAIT(0);
        __syncthreads();
        if (c < 15) {
            int kc = (c + 1) * 64;
            uint32_t nb = (c & 1) ? 0u : XS_STAGE;
#pragma unroll
            for (int i = 0; i < 4; i++) {
                int r = srow + 32 * i;
                uint32_t d = nb + SWZ((uint32_t)(r * 128 + colB * 2));
                cp_async16(sbase + XS_AH + d, g_fh + (size_t)(m0 + r) * 1024 + kc + colB);
                cp_async16(sbase + XS_AL + d, g_fl + (size_t)(m0 + r) * 1024 + kc + colB);
                cp_async16(sbase + XS_BH + d, g_Wih2 + (size_t)(n0 + r) * 2048 + kc + colB);
                cp_async16(sbase + XS_BL + d, g_Wih2 + (size_t)(n0 + r) * 2048 + 1024 + kc + colB);
            }
            CP_COMMIT();
        }

#pragma unroll
        for (int kk = 0; kk < 4; kk++) {
            uint32_t koff = (uint32_t)(kk * 32) + a_kb;
            uint32_t kboff = (uint32_t)(kk * 32) + b_kb;
            uint32_t Ah[2][4], Al[2][4], Bh[4][4], Bl[4][4];
#pragma unroll
            for (int mt = 0; mt < 2; mt++) {
                uint32_t rbase = (uint32_t)((wm * 32 + mt * 16 + a_lrow) * 128);
                ldsm_x4(Ah[mt][0], Ah[mt][1], Ah[mt][2], Ah[mt][3],
                        sb + XS_AH + SWZ(rbase + koff));
                ldsm_x4(Al[mt][0], Al[mt][1], Al[mt][2], Al[mt][3],
                        sb + XS_AL + SWZ(rbase + koff));
            }
#pragma unroll
            for (int ng = 0; ng < 4; ng++) {
                uint32_t rbase = (uint32_t)((wn * 64 + ng * 16 + b_lrow) * 128);
                ldsm_x4(Bh[ng][0], Bh[ng][1], Bh[ng][2], Bh[ng][3],
                        sb + XS_BH + SWZ(rbase + kboff));
                ldsm_x4(Bl[ng][0], Bl[ng][1], Bl[ng][2], Bl[ng][3],
                        sb + XS_BL + SWZ(rbase + kboff));
            }
#pragma unroll
            for (int mt = 0; mt < 2; mt++)
#pragma unroll
                for (int ng = 0; ng < 4; ng++) {
                    hmma16816(acc[mt][ng * 2],     Ah[mt][0], Ah[mt][1], Ah[mt][2], Ah[mt][3], Bh[ng][0], Bh[ng][1]);
                    hmma16816(acc[mt][ng * 2 + 1], Ah[mt][0], Ah[mt][1], Ah[mt][2], Ah[mt][3], Bh[ng][2], Bh[ng][3]);
                    hmma16816(acc[mt][ng * 2],     Ah[mt][0], Ah[mt][1], Ah[mt][2], Ah[mt][3], Bl[ng][0], Bl[ng][1]);
                    hmma16816(acc[mt][ng * 2 + 1], Ah[mt][0], Ah[mt][1], Ah[mt][2], Ah[mt][3], Bl[ng][2], Bl[ng][3]);
                    hmma16816(acc[mt][ng * 2],     Al[mt][0], Al[mt][1], Al[mt][2], Al[mt][3], Bh[ng][0], Bh[ng][1]);
                    hmma16816(acc[mt][ng * 2 + 1], Al[mt][0], Al[mt][1], Al[mt][2], Al[mt][3], Bh[ng][2], Bh[ng][3]);
                }
        }
    }

    // epilogue: add bias, store to g_xg (row m = t*64+b -> m*4096 + n)
#pragma unroll
    for (int mt = 0; mt < 2; mt++) {
        int row0 = m0 + wm * 32 + mt * 16 + r4;
#pragma unroll
        for (int nt = 0; nt < 8; nt++) {
            int n = n0 + wn * 64 + nt * 8 + c4 * 2;
            *(float2*)(g_xg + (size_t)row0 * G_ + n) =
                make_float2(acc[mt][nt][0] + bias2[nt].x, acc[mt][nt][1] + bias2[nt].y);
            *(float2*)(g_xg + (size_t)(row0 + 8) * G_ + n) =
                make_float2(acc[mt][nt][2] + bias2[nt].x, acc[mt][nt][3] + bias2[nt].y);
        }
    }
}

// ---------------- Phase B: persistent recurrence (unchanged from R11) --------
static constexpr uint32_t OFF_A0  = 0;          // 64KB stage buf 0
static constexpr uint32_t OFF_A1  = 65536;      // 64KB stage buf 1
static constexpr uint32_t OFF_WLO = 131072;     // 64KB resident W_lo
static constexpr uint32_t OFF_MB  = 196608;     // 2 mbarriers
static constexpr uint32_t OFF_S   = 0;          // ssum aliases A bufs (dead)
static constexpr uint32_t SMEM_USED = OFF_MB + 16;
static constexpr uint32_t SMEM_REQ  = SMEM_USED + 1024;

__global__ __launch_bounds__(256, 1) void lstm_persistent(
    const int* __restrict__ seq_len, float* __restrict__ out)
{
    extern __shared__ char dsm_raw[];
    uint32_t raw = smem_to_u32(dsm_raw);
    uint32_t sbase = (raw + 1023u) & ~1023u;
    char* sm = dsm_raw + (sbase - raw);

    int tid = threadIdx.x;
    int wid = tid >> 5, lane = tid & 31;
    int bx = blockIdx.x;
    int j0 = bx * 8;
    int grp = bx >> 5;

    int q8 = lane >> 3, r8 = lane & 7;
    uint32_t a_lrow = (uint32_t)(r8 + (q8 & 1) * 8);
    uint32_t a_kb   = (uint32_t)((q8 >> 1) * 16);
    uint32_t b_lrow = (uint32_t)(r8 + (q8 >> 1) * 8);
    uint32_t b_kb   = (uint32_t)((q8 & 1) * 16);

    if (tid == 0) {
        MBARRIER_INIT(sbase + OFF_MB, 1);
        MBARRIER_INIT(sbase + OFF_MB + 8, 1);
    }

    int sg[4];
#pragma unroll
    for (int i = 0; i < 4; i++) sg[i] = (grp + 1 + i) & 3;

    uint32_t wr[4][2][4][2];
    {
        int rr = tid >> 3;
        int cb = (tid & 7) * 8;
        int gn = (rr >> 3) * H_ + j0 + (rr & 7);
        const __nv_bfloat16* wrow = g_WW + (size_t)gn * 2048;
#pragma unroll
        for (int it = 0; it < 16; it++) {
            int col = it * 64 + cb;
            uint32_t soff = (uint32_t)((col >> 6) * 4096) +
                            SWZ((uint32_t)(rr * 128 + (col & 63) * 2));
            uint4 vh = *(const uint4*)(wrow + col);
            uint4 vl = *(const uint4*)(wrow + 1024 + col);
            *(uint4*)(sm + OFF_A0 + soff)  = vh;
            *(uint4*)(sm + OFF_WLO + soff) = vl;
        }
        __syncthreads();
#pragma unroll
        for (int i = 0; i < 4; i++)
#pragma unroll
            for (int kk = 0; kk < 2; kk++) {
                int scol = sg[i] * 256 + wid * 32 + kk * 16;
                uint32_t sub = (uint32_t)((scol >> 6) * 4096);
                uint32_t cin2 = (uint32_t)((scol & 63) * 2) + b_kb;
                ldsm_x4(wr[i][kk][0][0], wr[i][kk][0][1],
                        wr[i][kk][1][0], wr[i][kk][1][1],
                        sbase + OFF_A0 + sub + SWZ(b_lrow * 128 + cin2));
                ldsm_x4(wr[i][kk][2][0], wr[i][kk][2][1],
                        wr[i][kk][3][0], wr[i][kk][3][1],
                        sbase + OFF_A0 + sub + SWZ((b_lrow + 16) * 128 + cin2));
            }
        __syncthreads();
    }

    uint32_t asub0 = (uint32_t)(((wid * 32) >> 6) * 16384);
    uint32_t acin0 = (uint32_t)(((wid * 32) & 63) * 2) + a_kb;
    uint32_t asub1 = (uint32_t)(((wid * 32 + 16) >> 6) * 16384);
    uint32_t acin1 = (uint32_t)(((wid * 32 + 16) & 63) * 2) + a_kb;

    int eb0 = tid >> 3;
    int eb1 = eb0 + 32;
    int eu = tid & 7;
    int ej = j0 + eu;
    int sl0 = seq_len[eb0], sl1 = seq_len[eb1];
    float c0 = 0.f, c1 = 0.f;
    int hs = ej >> 8, hsub = (ej >> 6) & 3, hcin = ej & 63;
    uint32_t hbase = (uint32_t)((hs * 4 + hsub) * 16384);
    uint32_t hoff0 = hbase + SWZ((uint32_t)(eb0 * 128 + hcin * 2));
    uint32_t hoff0l = hbase + SWZ((uint32_t)((eb0 + 64) * 128 + hcin * 2));
    uint32_t hoff1 = hbase + SWZ((uint32_t)(eb1 * 128 + hcin * 2));
    uint32_t hoff1l = hbase + SWZ((uint32_t)((eb1 + 64) * 128 + hcin * 2));

    float* ssum = (float*)(sm + OFF_S);
    volatile unsigned* prod = (volatile unsigned*)g_prod;
    volatile unsigned* cons = (volatile unsigned*)&g_cons;
    uint32_t done0 = 0, done1 = 0;

    __syncthreads();

#pragma unroll 1
    for (int t = 0; t < T_; t++) {
        const uint8_t* __restrict__ hin2 = g_hh2[t & 1];
        uint8_t* __restrict__ hout2 = g_hh2[(t + 1) & 1];
        unsigned needp = 32u * (unsigned)t;

        if (tid == 0) {
            while (prod[sg[0]] < needp) { }
            MBARRIER_EXPECT_TX(sbase + OFF_MB, 65536);
            cp_bulk_g2s(sbase + OFF_A0, hin2 + sg[0] * 65536, 65536, sbase + OFF_MB);
            while (prod[sg[1]] < needp) { }
            MBARRIER_EXPECT_TX(sbase + OFF_MB + 8, 65536);
            cp_bulk_g2s(sbase + OFF_A1, hin2 + sg[1] * 65536, 65536, sbase + OFF_MB + 8);
        }

        float xr0[4], xr1[4];
        {
            const float* xa = g_xg + ((size_t)t * B_ + eb0) * G_ + ej;
            const float* xb = g_xg + ((size_t)t * B_ + eb1) * G_ + ej;
#pragma unroll
            for (int g4 = 0; g4 < 4; g4++) { xr0[g4] = xa[g4 * H_]; xr1[g4] = xb[g4 * H_]; }
        }

        float acc[4][4][4];
#pragma unroll
        for (int mt = 0; mt < 4; mt++)
#pragma unroll
            for (int nt = 0; nt < 4; nt++)
#pragma unroll
                for (int i = 0; i < 4; i++) acc[mt][nt][i] = 0.f;

#pragma unroll
        for (int i = 0; i < 4; i++) {
            uint32_t abuf = (i & 1) ? OFF_A1 : OFF_A0;
            if (i & 1) { MBARRIER_WAIT_PARITY(sbase + OFF_MB + 8, done1 & 1); done1++; }
            else       { MBARRIER_WAIT_PARITY(sbase + OFF_MB,     done0 & 1); done0++; }
            if (i == 3 && tid == 0) atomicAdd(&g_cons, 1u);

            int srt = sg[i];
#pragma unroll
            for (int kk = 0; kk < 2; kk++) {
                uint32_t atile = sbase + abuf + (kk ? asub1 : asub0);
                uint32_t cin2  = kk ? acin1 : acin0;
                int scol = srt * 256 + wid * 32 + kk * 16;
                uint32_t wsub = (uint32_t)((scol >> 6) * 4096);
                uint32_t wcin2 = (uint32_t)((scol & 63) * 2) + b_kb;

                uint32_t ah[4][4];
#pragma unroll
                for (int mt = 0; mt < 4; mt++)
                    ldsm_x4(ah[mt][0], ah[mt][1], ah[mt][2], ah[mt][3],
                            atile + SWZ((mt * 16 + a_lrow) * 128 + cin2));
                uint32_t wl[4][2];
                ldsm_x4(wl[0][0], wl[0][1], wl[1][0], wl[1][1],
                        sbase + OFF_WLO + wsub + SWZ(b_lrow * 128 + wcin2));
                ldsm_x4(wl[2][0], wl[2][1], wl[3][0], wl[3][1],
                        sbase + OFF_WLO + wsub + SWZ((b_lrow + 16) * 128 + wcin2));
#pragma unroll
                for (int mt = 0; mt < 4; mt++)
#pragma unroll
                    for (int nt = 0; nt < 4; nt++)
                        hmma16816(acc[mt][nt], ah[mt][0], ah[mt][1], ah[mt][2], ah[mt][3],
                                  wr[i][kk][nt][0], wr[i][kk][nt][1]);
#pragma unroll
                for (int mt = 0; mt < 4; mt++)
#pragma unroll
                    for (int nt = 0; nt < 4; nt++)
                        hmma16816(acc[mt][nt], ah[mt][0], ah[mt][1], ah[mt][2], ah[mt][3],
                                  wl[nt][0], wl[nt][1]);
#pragma unroll
                for (int mt = 0; mt < 4; mt++)
                    ldsm_x4(ah[mt][0], ah[mt][1], ah[mt][2], ah[mt][3],
                            atile + SWZ((64 + mt * 16 + a_lrow) * 128 + cin2));
#pragma unroll
                for (int mt = 0; mt < 4; mt++)
#pragma unroll
                    for (int nt = 0; nt < 4; nt++)
                        hmma16816(acc[mt][nt], ah[mt][0], ah[mt][1], ah[mt][2], ah[mt][3],
                                  wr[i][kk][nt][0], wr[i][kk][nt][1]);
            }
            __syncthreads();
            if (i < 2 && tid == 0) {
                while (prod[sg[i + 2]] < needp) { }
                uint32_t mb = sbase + OFF_MB + (i & 1) * 8;
                MBARRIER_EXPECT_TX(mb, 65536);
                cp_bulk_g2s(sbase + abuf, hin2 + sg[i + 2] * 65536, 65536, mb);
            }
        }

        {
            int r = lane >> 2, c4 = lane & 3;
            float* pp = ssum + wid * (64 * 34);
#pragma unroll
            for (int mt = 0; mt < 4; mt++)
#pragma unroll
                for (int nt = 0; nt < 4; nt++) {
                    int b1 = mt * 16 + r, n = nt * 8 + c4 * 2;
                    *(float2*)(pp + b1 * 34 + n) =
                        make_float2(acc[mt][nt][0], acc[mt][nt][1]);
                    *(float2*)(pp + (b1 + 8) * 34 + n) =
                        make_float2(acc[mt][nt][2], acc[mt][nt][3]);
                }
        }
        __syncthreads();

        if (tid == 0) {
            unsigned needc = 128u * (unsigned)t;
            while (*cons < needc) { }
        }
        __syncthreads();

#pragma unroll
        for (int it = 0; it < 2; it++) {
            int b = it ? eb1 : eb0;
            float gate[4];
#pragma unroll
            for (int g4 = 0; g4 < 4; g4++) {
                int n = g4 * 8 + eu;
                float s0 = 0.f;
#pragma unroll
                for (int w = 0; w < 8; w++)
                    s0 += ssum[w * (64 * 34) + b * 34 + n];
                gate[g4] = s0 + (it ? xr1[g4] : xr0[g4]);
            }
            float si = sigf(gate[0]);
            float sf = sigf(gate[1]);
            float tg = tanh_fast(gate[2]);
            float so = sigf(gate[3]);
            float cn = fmaf(sf, it ? c1 : c0, si * tg);
            if (it) c1 = cn; else c0 = cn;
            float hn = so * tanh_fast(cn);
            __nv_bfloat16 hi = __float2bfloat16(hn);
            __nv_bfloat16 lo = __float2bfloat16(hn - __bfloat162float(hi));
            *(__nv_bfloat16*)(hout2 + (it ? hoff1 : hoff0)) = hi;
            *(__nv_bfloat16*)(hout2 + (it ? hoff1l : hoff0l)) = lo;
            out[((size_t)b * T_ + t) * H_ + ej] = (t < (it ? sl1 : sl0)) ? hn : 0.f;
        }

        __threadfence();
        __syncthreads();
        if (tid == 0) atomicAdd(&g_prod[grp], 1u);
    }
}

extern "C" void kernel_launch(void* const* d_in, const int* in_sizes, int n_in,
                              void* d_out, int out_size)
{
    const float* feature = (const float*)d_in[0];
    const float* W_ih    = (const float*)d_in[1];
    const float* W_hh    = (const float*)d_in[2];
    const float* b_ih    = (const float*)d_in[3];
    const float* b_hh    = (const float*)d_in[4];
    const int*   seq_len = (const int*)d_in[5];
    float* out = (float*)d_out;

    cudaFuncSetAttribute(lstm_persistent, cudaFuncAttributeMaxDynamicSharedMemorySize,
                         SMEM_REQ);
    cudaFuncSetAttribute(gemm_xg_tc, cudaFuncAttributeMaxDynamicSharedMemorySize,
                         XS_REQ);

    init_state_kernel<<<(131072 + 255) / 256, 256>>>();
    build_WW_kernel<<<(G_ * H_ + 255) / 256, 256>>>(W_hh);
    build_Wih2_kernel<<<(G_ * D_ + 255) / 256, 256>>>(W_ih);
    build_fA_kernel<<<(T_ * B_ * D_ + 255) / 256, 256>>>(feature);
    gemm_xg_tc<<<dim3(256, 32), 256, XS_REQ>>>(b_ih, b_hh);
    lstm_persistent<<<128, 256, SMEM_REQ>>>(seq_len, out);
}

// round 13
// speedup vs baseline: 3.0760x; 1.2150x over previous
#include <cuda_runtime.h>
#include <cuda_fp16.h>
#include <math.h>
#include <stdint.h>

#define B_ 64
#define T_ 512
#define D_ 1024
#define H_ 1024
#define G_ 4096

// ---------------- device scratch (allocation-free rule) ----------------
__device__ float g_xg[(size_t)T_ * B_ * G_];            // [T][B][4H] pre-activations
// h ping-pong as SW128-swizzled image: [pp][stage][sub][64 rows][128B] = 128KB each
__device__ __align__(128) uint8_t g_hh2[2][4 * 4 * 64 * 128];
__device__ __half g_WW[(size_t)G_ * 2 * H_];            // W_hh [4096][2048]: hi | lo
__device__ __half g_Wih2[(size_t)G_ * 2 * D_];          // W_ih hi | lo
__device__ __half g_fh[(size_t)T_ * B_ * D_];           // feature fp16, rows m = t*64+b
__device__ unsigned g_prod[4];                          // per-group producer counters
__device__ unsigned g_cons;                             // consumption counter

#define SWZ(off) ((off) ^ (((off) >> 3) & 0x70))

__device__ __forceinline__ uint32_t smem_to_u32(const void* p) {
    uint32_t a;
    asm("{ .reg .u64 t; cvta.to.shared.u64 t, %1; cvt.u32.u64 %0, t; }" : "=r"(a) : "l"(p));
    return a;
}

__device__ __forceinline__ void ldsm_x4(uint32_t& r0, uint32_t& r1, uint32_t& r2,
                                        uint32_t& r3, uint32_t addr) {
    asm volatile("ldmatrix.sync.aligned.m8n8.x4.shared.b16 {%0,%1,%2,%3}, [%4];"
                 : "=r"(r0), "=r"(r1), "=r"(r2), "=r"(r3) : "r"(addr));
}

__device__ __forceinline__ void hmma16816(float* d, uint32_t a0, uint32_t a1,
                                          uint32_t a2, uint32_t a3,
                                          uint32_t b0, uint32_t b1) {
    asm volatile(
        "mma.sync.aligned.m16n8k16.row.col.f32.f16.f16.f32 "
        "{%0,%1,%2,%3}, {%4,%5,%6,%7}, {%8,%9}, {%0,%1,%2,%3};"
        : "+f"(d[0]), "+f"(d[1]), "+f"(d[2]), "+f"(d[3])
        : "r"(a0), "r"(a1), "r"(a2), "r"(a3), "r"(b0), "r"(b1));
}

__device__ __forceinline__ void cp_async16(uint32_t dst, const void* src) {
    asm volatile("cp.async.cg.shared.global [%0], [%1], 16;"
                 :: "r"(dst), "l"(src) : "memory");
}
#define CP_COMMIT() asm volatile("cp.async.commit_group;" ::: "memory")
#define CP_WAIT(N)  asm volatile("cp.async.wait_group %0;" :: "n"(N) : "memory")

__device__ __forceinline__ void cp_bulk_g2s(uint32_t dst, const void* src,
                                            uint32_t bytes, uint32_t mbar) {
    asm volatile(
        "cp.async.bulk.shared::cta.global.mbarrier::complete_tx::bytes [%0], [%1], %2, [%3];"
        :: "r"(dst), "l"(src), "r"(bytes), "r"(mbar) : "memory");
}
#define MBARRIER_INIT(addr, cnt) \
    asm volatile("mbarrier.init.shared.b64 [%0], %1;" :: "r"((uint32_t)(addr)), "r"((uint32_t)(cnt)) : "memory")
#define MBARRIER_EXPECT_TX(addr, bytes) \
    asm volatile("mbarrier.arrive.expect_tx.shared.b64 _, [%0], %1;" \
        :: "r"((uint32_t)(addr)), "r"((uint32_t)(bytes)) : "memory")
#define MBARRIER_WAIT_PARITY(mbar_smem_addr, phase_parity) do { \
    uint32_t _mbar = (uint32_t)(mbar_smem_addr); \
    uint32_t _parity = (uint32_t)(phase_parity); \
    uint32_t _done; \
    asm volatile( \
        "{\n\t.reg .pred p;\n\t" \
        "mbarrier.try_wait.parity.acquire.cta.shared::cta.b64 p, [%1], %2;\n\t" \
        "selp.b32 %0, 1, 0, p;\n\t}" \
        : "=r"(_done) : "r"(_mbar), "r"(_parity) : "memory"); \
    if (!_done) { \
        asm volatile( \
            "{\n\t.reg .pred P1;\n\t" \
            "WAIT_LOOP_%=:\n\t" \
            "mbarrier.try_wait.parity.acquire.cta.shared::cta.b64 P1, [%0], %1, 0x989680;\n\t" \
            "@P1 bra.uni WAIT_DONE_%=;\n\t" \
            "bra.uni WAIT_LOOP_%=;\n\t" \
            "WAIT_DONE_%=:\n\t}" \
            :: "r"(_mbar), "r"(_parity) : "memory"); \
    } \
} while(0)

__device__ __forceinline__ float sigf(float x) {
    return __fdividef(1.f, 1.f + __expf(-x));
}
__device__ __forceinline__ float tanh_fast(float x) {
    x = fminf(fmaxf(x, -15.f), 15.f);
    float e = __expf(2.f * x);
    return __fdividef(e - 1.f, e + 1.f);
}

// ---------------- init / prep kernels ----------------
__global__ void init_state_kernel() {
    int i = blockIdx.x * blockDim.x + threadIdx.x;
    if (i < 65536) ((uint32_t*)g_hh2)[i] = 0u;   // 2 x 128KB
    if (i < 4) g_prod[i] = 0u;
    if (i == 4) g_cons = 0u;
}

__global__ void build_WW_kernel(const float* __restrict__ W_hh) {
    int i = blockIdx.x * blockDim.x + threadIdx.x;
    if (i < G_ * H_) {
        int row = i >> 10, col = i & 1023;
        float w = W_hh[i];
        __half hi = __float2half(w);
        __half lo = __float2half(w - __half2float(hi));
        g_WW[(size_t)row * 2048 + col] = hi;
        g_WW[(size_t)row * 2048 + 1024 + col] = lo;
    }
}

__global__ void build_Wih2_kernel(const float* __restrict__ W_ih) {
    int i = blockIdx.x * blockDim.x + threadIdx.x;
    if (i < G_ * D_) {
        int row = i >> 10, col = i & 1023;
        float w = W_ih[i];
        __half hi = __float2half(w);
        __half lo = __float2half(w - __half2float(hi));
        g_Wih2[(size_t)row * 2048 + col] = hi;
        g_Wih2[(size_t)row * 2048 + 1024 + col] = lo;
    }
}

// feature [b][t][d] -> f fp16, rows m = t*64+b
__global__ void build_fA_kernel(const float* __restrict__ feature) {
    size_t i = (size_t)blockIdx.x * blockDim.x + threadIdx.x;
    if (i < (size_t)T_ * B_ * D_) {
        int k = (int)(i & 1023);
        int m = (int)(i >> 10);
        int tt = m >> 6, b = m & 63;
        g_fh[i] = __float2half(feature[((size_t)b * T_ + tt) * D_ + k]);
    }
}

// ---------------- Phase A: x_gates GEMM via HMMA fp16 (2-pass W split) --------
static constexpr uint32_t XS_AH = 0;        // 16KB
static constexpr uint32_t XS_BH = 16384;
static constexpr uint32_t XS_BL = 32768;
static constexpr uint32_t XS_STAGE = 49152;
static constexpr uint32_t XS_REQ = 2 * XS_STAGE + 1024;

__global__ __launch_bounds__(256, 1) void gemm_xg_tc(
    const float* __restrict__ b_ih, const float* __restrict__ b_hh)
{
    extern __shared__ char dsm_raw[];
    uint32_t raw = smem_to_u32(dsm_raw);
    uint32_t sbase = (raw + 1023u) & ~1023u;
    char* sm = dsm_raw + (sbase - raw);

    int tid = threadIdx.x;
    int wid = tid >> 5, lane = tid & 31;
    int m0 = blockIdx.x * 128;
    int n0 = blockIdx.y * 128;
    int wm = wid >> 1, wn = wid & 1;

    int q8 = lane >> 3, r8 = lane & 7;
    uint32_t a_lrow = (uint32_t)(r8 + (q8 & 1) * 8);
    uint32_t a_kb   = (uint32_t)((q8 >> 1) * 16);
    uint32_t b_lrow = (uint32_t)(r8 + (q8 >> 1) * 8);
    uint32_t b_kb   = (uint32_t)((q8 & 1) * 16);

    int srow = tid >> 3;
    int colB = (tid & 7) * 8;

    int r4 = lane >> 2, c4 = lane & 3;
    float2 bias2[8];
#pragma unroll
    for (int nt = 0; nt < 8; nt++) {
        int n = n0 + wn * 64 + nt * 8 + c4 * 2;
        bias2[nt] = make_float2(b_ih[n] + b_hh[n], b_ih[n + 1] + b_hh[n + 1]);
    }

    float acc[2][8][4];
#pragma unroll
    for (int mt = 0; mt < 2; mt++)
#pragma unroll
        for (int nt = 0; nt < 8; nt++)
#pragma unroll
            for (int i = 0; i < 4; i++) acc[mt][nt][i] = 0.f;

    {
#pragma unroll
        for (int i = 0; i < 4; i++) {
            int r = srow + 32 * i;
            uint32_t d = SWZ((uint32_t)(r * 128 + colB * 2));
            cp_async16(sbase + XS_AH + d, g_fh + (size_t)(m0 + r) * 1024 + colB);
            cp_async16(sbase + XS_BH + d, g_Wih2 + (size_t)(n0 + r) * 2048 + colB);
            cp_async16(sbase + XS_BL + d, g_Wih2 + (size_t)(n0 + r) * 2048 + 1024 + colB);
        }
        CP_COMMIT();
    }

#pragma unroll 1
    for (int c = 0; c < 16; c++) {
        uint32_t sb = sbase + (c & 1) * XS_STAGE;
        CP_WAIT(0);
        __syncthreads();
        if (c < 15) {
            int kc = (c + 1) * 64;
            uint32_t nb = (c & 1) ? 0u : XS_STAGE;
#pragma unroll
            for (int i = 0; i < 4; i++) {
                int r = srow + 32 * i;
                uint32_t d = nb + SWZ((uint32_t)(r * 128 + colB * 2));
                cp_async16(sbase + XS_AH + d, g_fh + (size_t)(m0 + r) * 1024 + kc + colB);
                cp_async16(sbase + XS_BH + d, g_Wih2 + (size_t)(n0 + r) * 2048 + kc + colB);
                cp_async16(sbase + XS_BL + d, g_Wih2 + (size_t)(n0 + r) * 2048 + 1024 + kc + colB);
            }
            CP_COMMIT();
        }

#pragma unroll
        for (int kk = 0; kk < 4; kk++) {
            uint32_t koff = (uint32_t)(kk * 32) + a_kb;
            uint32_t kboff = (uint32_t)(kk * 32) + b_kb;
            uint32_t Ah[2][4], Bh[4][4], Bl[4][4];
#pragma unroll
            for (int mt = 0; mt < 2; mt++) {
                uint32_t rbase = (uint32_t)((wm * 32 + mt * 16 + a_lrow) * 128);
                ldsm_x4(Ah[mt][0], Ah[mt][1], Ah[mt][2], Ah[mt][3],
                        sb + XS_AH + SWZ(rbase + koff));
            }
#pragma unroll
            for (int ng = 0; ng < 4; ng++) {
                uint32_t rbase = (uint32_t)((wn * 64 + ng * 16 + b_lrow) * 128);
                ldsm_x4(Bh[ng][0], Bh[ng][1], Bh[ng][2], Bh[ng][3],
                        sb + XS_BH + SWZ(rbase + kboff));
                ldsm_x4(Bl[ng][0], Bl[ng][1], Bl[ng][2], Bl[ng][3],
                        sb + XS_BL + SWZ(rbase + kboff));
            }
#pragma unroll
            for (int mt = 0; mt < 2; mt++)
#pragma unroll
                for (int ng = 0; ng < 4; ng++) {
                    hmma16816(acc[mt][ng * 2],     Ah[mt][0], Ah[mt][1], Ah[mt][2], Ah[mt][3], Bh[ng][0], Bh[ng][1]);
                    hmma16816(acc[mt][ng * 2 + 1], Ah[mt][0], Ah[mt][1], Ah[mt][2], Ah[mt][3], Bh[ng][2], Bh[ng][3]);
                    hmma16816(acc[mt][ng * 2],     Ah[mt][0], Ah[mt][1], Ah[mt][2], Ah[mt][3], Bl[ng][0], Bl[ng][1]);
                    hmma16816(acc[mt][ng * 2 + 1], Ah[mt][0], Ah[mt][1], Ah[mt][2], Ah[mt][3], Bl[ng][2], Bl[ng][3]);
                }
        }
    }

#pragma unroll
    for (int mt = 0; mt < 2; mt++) {
        int row0 = m0 + wm * 32 + mt * 16 + r4;
#pragma unroll
        for (int nt = 0; nt < 8; nt++) {
            int n = n0 + wn * 64 + nt * 8 + c4 * 2;
            *(float2*)(g_xg + (size_t)row0 * G_ + n) =
                make_float2(acc[mt][nt][0] + bias2[nt].x, acc[mt][nt][1] + bias2[nt].y);
            *(float2*)(g_xg + (size_t)(row0 + 8) * G_ + n) =
                make_float2(acc[mt][nt][2] + bias2[nt].x, acc[mt][nt][3] + bias2[nt].y);
        }
    }
}

// ---------------- Phase B: persistent recurrence (fp16, 2-pass W) -------------
// Grid 128 x 256 thr. Same group-synced pipeline as R12; A = h only (64 rows),
// stages 32KB. acc[64][32] += h@W_hi + h@W_lo per K-slice.
static constexpr uint32_t OFF_A0  = 0;          // 32KB stage buf 0
static constexpr uint32_t OFF_A1  = 32768;      // 32KB stage buf 1
static constexpr uint32_t OFF_WLO = 65536;      // 64KB resident W_lo
static constexpr uint32_t OFF_MB  = 131072;     // 2 mbarriers
static constexpr uint32_t OFF_S   = 131136;     // ssum [8][64][34] f32 dedicated
static constexpr uint32_t SMEM_USED = OFF_S + 8 * 64 * 34 * 4;
static constexpr uint32_t SMEM_REQ  = SMEM_USED + 1024;

__global__ __launch_bounds__(256, 1) void lstm_persistent(
    const int* __restrict__ seq_len, float* __restrict__ out)
{
    extern __shared__ char dsm_raw[];
    uint32_t raw = smem_to_u32(dsm_raw);
    uint32_t sbase = (raw + 1023u) & ~1023u;
    char* sm = dsm_raw + (sbase - raw);

    int tid = threadIdx.x;
    int wid = tid >> 5, lane = tid & 31;
    int bx = blockIdx.x;
    int j0 = bx * 8;
    int grp = bx >> 5;

    int q8 = lane >> 3, r8 = lane & 7;
    uint32_t a_lrow = (uint32_t)(r8 + (q8 & 1) * 8);
    uint32_t a_kb   = (uint32_t)((q8 >> 1) * 16);
    uint32_t b_lrow = (uint32_t)(r8 + (q8 >> 1) * 8);
    uint32_t b_kb   = (uint32_t)((q8 & 1) * 16);

    if (tid == 0) {
        MBARRIER_INIT(sbase + OFF_MB, 1);
        MBARRIER_INIT(sbase + OFF_MB + 8, 1);
    }

    int sg[4];
#pragma unroll
    for (int i = 0; i < 4; i++) sg[i] = (grp + 1 + i) & 3;

    // ---- load W_hi into WLO temp, ldsm to regs; then load W_lo resident ----
    uint32_t wr[4][2][4][2];
    {
        int rr = tid >> 3;
        int cb = (tid & 7) * 8;
        int gn = (rr >> 3) * H_ + j0 + (rr & 7);
        const __half* wrow = g_WW + (size_t)gn * 2048;
#pragma unroll
        for (int it = 0; it < 16; it++) {
            int col = it * 64 + cb;
            uint32_t soff = (uint32_t)((col >> 6) * 4096) +
                            SWZ((uint32_t)(rr * 128 + (col & 63) * 2));
            *(uint4*)(sm + OFF_WLO + soff) = *(const uint4*)(wrow + col);   // hi (temp)
        }
        __syncthreads();
#pragma unroll
        for (int i = 0; i < 4; i++)
#pragma unroll
            for (int kk = 0; kk < 2; kk++) {
                int scol = sg[i] * 256 + wid * 32 + kk * 16;
                uint32_t sub = (uint32_t)((scol >> 6) * 4096);
                uint32_t cin2 = (uint32_t)((scol & 63) * 2) + b_kb;
                ldsm_x4(wr[i][kk][0][0], wr[i][kk][0][1],
                        wr[i][kk][1][0], wr[i][kk][1][1],
                        sbase + OFF_WLO + sub + SWZ(b_lrow * 128 + cin2));
                ldsm_x4(wr[i][kk][2][0], wr[i][kk][2][1],
                        wr[i][kk][3][0], wr[i][kk][3][1],
                        sbase + OFF_WLO + sub + SWZ((b_lrow + 16) * 128 + cin2));
            }
        __syncthreads();
#pragma unroll
        for (int it = 0; it < 16; it++) {
            int col = it * 64 + cb;
            uint32_t soff = (uint32_t)((col >> 6) * 4096) +
                            SWZ((uint32_t)(rr * 128 + (col & 63) * 2));
            *(uint4*)(sm + OFF_WLO + soff) = *(const uint4*)(wrow + 1024 + col);  // lo
        }
        __syncthreads();
    }

    // per-warp A ldsm constants (subtile = 8KB: 64 cols x 64 rows)
    uint32_t asub0 = (uint32_t)(((wid * 32) >> 6) * 8192);
    uint32_t acin0 = (uint32_t)(((wid * 32) & 63) * 2) + a_kb;
    uint32_t asub1 = (uint32_t)(((wid * 32 + 16) >> 6) * 8192);
    uint32_t acin1 = (uint32_t)(((wid * 32 + 16) & 63) * 2) + a_kb;

    int eb0 = tid >> 3;
    int eb1 = eb0 + 32;
    int eu = tid & 7;
    int ej = j0 + eu;
    int sl0 = seq_len[eb0], sl1 = seq_len[eb1];
    float c0 = 0.f, c1 = 0.f;
    int hs = ej >> 8, hsub = (ej >> 6) & 3, hcin = ej & 63;
    uint32_t hbase = (uint32_t)((hs * 4 + hsub) * 8192);
    uint32_t hoff0 = hbase + SWZ((uint32_t)(eb0 * 128 + hcin * 2));
    uint32_t hoff1 = hbase + SWZ((uint32_t)(eb1 * 128 + hcin * 2));

    float* ssum = (float*)(sm + OFF_S);
    volatile unsigned* prod = (volatile unsigned*)g_prod;
    volatile unsigned* cons = (volatile unsigned*)&g_cons;
    uint32_t done0 = 0, done1 = 0;

    __syncthreads();

#pragma unroll 1
    for (int t = 0; t < T_; t++) {
        const uint8_t* __restrict__ hin2 = g_hh2[t & 1];
        uint8_t* __restrict__ hout2 = g_hh2[(t + 1) & 1];
        unsigned needp = 32u * (unsigned)t;

        if (tid == 0) {
            while (prod[sg[0]] < needp) { }
            MBARRIER_EXPECT_TX(sbase + OFF_MB, 32768);
            cp_bulk_g2s(sbase + OFF_A0, hin2 + sg[0] * 32768, 32768, sbase + OFF_MB);
            while (prod[sg[1]] < needp) { }
            MBARRIER_EXPECT_TX(sbase + OFF_MB + 8, 32768);
            cp_bulk_g2s(sbase + OFF_A1, hin2 + sg[1] * 32768, 32768, sbase + OFF_MB + 8);
        }

        float xr0[4], xr1[4];
        {
            const float* xa = g_xg + ((size_t)t * B_ + eb0) * G_ + ej;
            const float* xb = g_xg + ((size_t)t * B_ + eb1) * G_ + ej;
#pragma unroll
            for (int g4 = 0; g4 < 4; g4++) { xr0[g4] = xa[g4 * H_]; xr1[g4] = xb[g4 * H_]; }
        }

        float acc[4][4][4];
#pragma unroll
        for (int mt = 0; mt < 4; mt++)
#pragma unroll
            for (int nt = 0; nt < 4; nt++)
#pragma unroll
                for (int i = 0; i < 4; i++) acc[mt][nt][i] = 0.f;

#pragma unroll
        for (int i = 0; i < 4; i++) {
            uint32_t abuf = (i & 1) ? OFF_A1 : OFF_A0;
            if (i & 1) { MBARRIER_WAIT_PARITY(sbase + OFF_MB + 8, done1 & 1); done1++; }
            else       { MBARRIER_WAIT_PARITY(sbase + OFF_MB,     done0 & 1); done0++; }
            if (i == 3 && tid == 0) atomicAdd(&g_cons, 1u);

#pragma unroll
            for (int kk = 0; kk < 2; kk++) {
                uint32_t atile = sbase + abuf + (kk ? asub1 : asub0);
                uint32_t cin2  = kk ? acin1 : acin0;
                int scol = sg[i] * 256 + wid * 32 + kk * 16;
                uint32_t wsub = (uint32_t)((scol >> 6) * 4096);
                uint32_t wcin2 = (uint32_t)((scol & 63) * 2) + b_kb;

                uint32_t ah[4][4];
#pragma unroll
                for (int mt = 0; mt < 4; mt++)
                    ldsm_x4(ah[mt][0], ah[mt][1], ah[mt][2], ah[mt][3],
                            atile + SWZ((mt * 16 + a_lrow) * 128 + cin2));
                uint32_t wl[4][2];
                ldsm_x4(wl[0][0], wl[0][1], wl[1][0], wl[1][1],
                        sbase + OFF_WLO + wsub + SWZ(b_lrow * 128 + wcin2));
                ldsm_x4(wl[2][0], wl[2][1], wl[3][0], wl[3][1],
                        sbase + OFF_WLO + wsub + SWZ((b_lrow + 16) * 128 + wcin2));
#pragma unroll
                for (int mt = 0; mt < 4; mt++)
#pragma unroll
                    for (int nt = 0; nt < 4; nt++)
                        hmma16816(acc[mt][nt], ah[mt][0], ah[mt][1], ah[mt][2], ah[mt][3],
                                  wr[i][kk][nt][0], wr[i][kk][nt][1]);
#pragma unroll
                for (int mt = 0; mt < 4; mt++)
#pragma unroll
                    for (int nt = 0; nt < 4; nt++)
                        hmma16816(acc[mt][nt], ah[mt][0], ah[mt][1], ah[mt][2], ah[mt][3],
                                  wl[nt][0], wl[nt][1]);
            }
            __syncthreads();
            if (i < 2 && tid == 0) {
                while (prod[sg[i + 2]] < needp) { }
                uint32_t mb = sbase + OFF_MB + (i & 1) * 8;
                MBARRIER_EXPECT_TX(mb, 32768);
                cp_bulk_g2s(sbase + abuf, hin2 + sg[i + 2] * 32768, 32768, mb);
            }
        }

        {
            int r = lane >> 2, c4 = lane & 3;
            float* pp = ssum + wid * (64 * 34);
#pragma unroll
            for (int mt = 0; mt < 4; mt++)
#pragma unroll
                for (int nt = 0; nt < 4; nt++) {
                    int b1 = mt * 16 + r, n = nt * 8 + c4 * 2;
                    *(float2*)(pp + b1 * 34 + n) =
                        make_float2(acc[mt][nt][0], acc[mt][nt][1]);
                    *(float2*)(pp + (b1 + 8) * 34 + n) =
                        make_float2(acc[mt][nt][2], acc[mt][nt][3]);
                }
        }
        __syncthreads();

        if (tid == 0) {
            unsigned needc = 128u * (unsigned)t;
            while (*cons < needc) { }
        }
        __syncthreads();

#pragma unroll
        for (int it = 0; it < 2; it++) {
            int b = it ? eb1 : eb0;
            float gate[4];
#pragma unroll
            for (int g4 = 0; g4 < 4; g4++) {
                int n = g4 * 8 + eu;
                float s0 = 0.f;
#pragma unroll
                for (int w = 0; w < 8; w++)
                    s0 += ssum[w * (64 * 34) + b * 34 + n];
                gate[g4] = s0 + (it ? xr1[g4] : xr0[g4]);
            }
            float si = sigf(gate[0]);
            float sf = sigf(gate[1]);
            float tg = tanh_fast(gate[2]);
            float so = sigf(gate[3]);
            float cn = fmaf(sf, it ? c1 : c0, si * tg);
            if (it) c1 = cn; else c0 = cn;
            float hn = so * tanh_fast(cn);
            *(__half*)(hout2 + (it ? hoff1 : hoff0)) = __float2half(hn);
            out[((size_t)b * T_ + t) * H_ + ej] = (t < (it ? sl1 : sl0)) ? hn : 0.f;
        }

        __threadfence();
        __syncthreads();
        if (tid == 0) atomicAdd(&g_prod[grp], 1u);
    }
}

extern "C" void kernel_launch(void* const* d_in, const int* in_sizes, int n_in,
                              void* d_out, int out_size)
{
    const float* feature = (const float*)d_in[0];
    const float* W_ih    = (const float*)d_in[1];
    const float* W_hh    = (const float*)d_in[2];
    const float* b_ih    = (const float*)d_in[3];
    const float* b_hh    = (const float*)d_in[4];
    const int*   seq_len = (const int*)d_in[5];
    float* out = (float*)d_out;

    cudaFuncSetAttribute(lstm_persistent, cudaFuncAttributeMaxDynamicSharedMemorySize,
                         SMEM_REQ);
    cudaFuncSetAttribute(gemm_xg_tc, cudaFuncAttributeMaxDynamicSharedMemorySize,
                         XS_REQ);

    init_state_kernel<<<(T_ * B_ * D_ / 256 + 1), 256>>>();
    build_WW_kernel<<<(G_ * H_ + 255) / 256, 256>>>(W_hh);
    build_Wih2_kernel<<<(G_ * D_ + 255) / 256, 256>>>(W_ih);
    build_fA_kernel<<<(T_ * B_ * D_ + 255) / 256, 256>>>(feature);
    gemm_xg_tc<<<dim3(256, 32), 256, XS_REQ>>>(b_ih, b_hh);
    lstm_persistent<<<128, 256, SMEM_REQ>>>(seq_len, out);
}

// round 15
// speedup vs baseline: 3.5112x; 1.1415x over previous
#include <cuda_runtime.h>
#include <cuda_fp16.h>
#include <math.h>
#include <stdint.h>

#define B_ 64
#define T_ 512
#define D_ 1024
#define H_ 1024
#define G_ 4096

// ---------------- device scratch (allocation-free rule) ----------------
__device__ float g_xg[(size_t)T_ * B_ * G_];            // [T][B][4H] pre-activations
// h ping-pong as SW128-swizzled image: [pp][stage][sub][64 rows][128B] = 128KB each
__device__ __align__(128) uint8_t g_hh2[2][4 * 4 * 64 * 128];
__device__ __half g_WW[(size_t)G_ * 2 * H_];            // W_hh [4096][2048]: hi | lo
__device__ __half g_Wih[(size_t)G_ * D_];               // W_ih fp16 single-pass
__device__ __half g_fh[(size_t)T_ * B_ * D_];           // feature fp16, rows m = t*64+b
__device__ unsigned g_prod[4];                          // per-group producer counters
__device__ unsigned g_cons;                             // consumption counter

#define SWZ(off) ((off) ^ (((off) >> 3) & 0x70))

__device__ __forceinline__ uint32_t smem_to_u32(const void* p) {
    uint32_t a;
    asm("{ .reg .u64 t; cvta.to.shared.u64 t, %1; cvt.u32.u64 %0, t; }" : "=r"(a) : "l"(p));
    return a;
}

__device__ __forceinline__ void ldsm_x4(uint32_t& r0, uint32_t& r1, uint32_t& r2,
                                        uint32_t& r3, uint32_t addr) {
    asm volatile("ldmatrix.sync.aligned.m8n8.x4.shared.b16 {%0,%1,%2,%3}, [%4];"
                 : "=r"(r0), "=r"(r1), "=r"(r2), "=r"(r3) : "r"(addr));
}

__device__ __forceinline__ void hmma16816(float* d, uint32_t a0, uint32_t a1,
                                          uint32_t a2, uint32_t a3,
                                          uint32_t b0, uint32_t b1) {
    asm volatile(
        "mma.sync.aligned.m16n8k16.row.col.f32.f16.f16.f32 "
        "{%0,%1,%2,%3}, {%4,%5,%6,%7}, {%8,%9}, {%0,%1,%2,%3};"
        : "+f"(d[0]), "+f"(d[1]), "+f"(d[2]), "+f"(d[3])
        : "r"(a0), "r"(a1), "r"(a2), "r"(a3), "r"(b0), "r"(b1));
}

__device__ __forceinline__ void cp_async16(uint32_t dst, const void* src) {
    asm volatile("cp.async.cg.shared.global [%0], [%1], 16;"
                 :: "r"(dst), "l"(src) : "memory");
}
#define CP_COMMIT() asm volatile("cp.async.commit_group;" ::: "memory")
#define CP_WAIT(N)  asm volatile("cp.async.wait_group %0;" :: "n"(N) : "memory")

__device__ __forceinline__ void cp_bulk_g2s(uint32_t dst, const void* src,
                                            uint32_t bytes, uint32_t mbar) {
    asm volatile(
        "cp.async.bulk.shared::cta.global.mbarrier::complete_tx::bytes [%0], [%1], %2, [%3];"
        :: "r"(dst), "l"(src), "r"(bytes), "r"(mbar) : "memory");
}
#define MBARRIER_INIT(addr, cnt) \
    asm volatile("mbarrier.init.shared.b64 [%0], %1;" :: "r"((uint32_t)(addr)), "r"((uint32_t)(cnt)) : "memory")
#define MBARRIER_EXPECT_TX(addr, bytes) \
    asm volatile("mbarrier.arrive.expect_tx.shared.b64 _, [%0], %1;" \
        :: "r"((uint32_t)(addr)), "r"((uint32_t)(bytes)) : "memory")
#define MBARRIER_WAIT_PARITY(mbar_smem_addr, phase_parity) do { \
    uint32_t _mbar = (uint32_t)(mbar_smem_addr); \
    uint32_t _parity = (uint32_t)(phase_parity); \
    uint32_t _done; \
    asm volatile( \
        "{\n\t.reg .pred p;\n\t" \
        "mbarrier.try_wait.parity.acquire.cta.shared::cta.b64 p, [%1], %2;\n\t" \
        "selp.b32 %0, 1, 0, p;\n\t}" \
        : "=r"(_done) : "r"(_mbar), "r"(_parity) : "memory"); \
    if (!_done) { \
        asm volatile( \
            "{\n\t.reg .pred P1;\n\t" \
            "WAIT_LOOP_%=:\n\t" \
            "mbarrier.try_wait.parity.acquire.cta.shared::cta.b64 P1, [%0], %1, 0x989680;\n\t" \
            "@P1 bra.uni WAIT_DONE_%=;\n\t" \
            "bra.uni WAIT_LOOP_%=;\n\t" \
            "WAIT_DONE_%=:\n\t}" \
            :: "r"(_mbar), "r"(_parity) : "memory"); \
    } \
} while(0)

__device__ __forceinline__ float sigf(float x) {
    return __fdividef(1.f, 1.f + __expf(-x));
}
__device__ __forceinline__ float tanh_fast(float x) {
    x = fminf(fmaxf(x, -15.f), 15.f);
    float e = __expf(2.f * x);
    return __fdividef(e - 1.f, e + 1.f);
}

__device__ __forceinline__ uint2 pack4h(float a, float b, float c, float d) {
    __half2 p0 = __floats2half2_rn(a, b);
    __half2 p1 = __floats2half2_rn(c, d);
    uint2 r;
    r.x = *(uint32_t*)&p0;
    r.y = *(uint32_t*)&p1;
    return r;
}

// ---------------- init / prep kernels ----------------
__global__ void init_state_kernel() {
    int i = blockIdx.x * blockDim.x + threadIdx.x;
    if (i < 65536) ((uint32_t*)g_hh2)[i] = 0u;   // 2 x 128KB
    if (i < 4) g_prod[i] = 0u;
    if (i == 4) g_cons = 0u;
}

// W_hh -> hi|lo fp16 (vectorized: 4 cols/thread)
__global__ void build_WW_kernel(const float* __restrict__ W_hh) {
    int i = blockIdx.x * blockDim.x + threadIdx.x;
    if (i < G_ * H_ / 4) {
        int row = i >> 8;
        int col4 = (i & 255) * 4;
        float4 w = *(const float4*)(W_hh + (size_t)row * 1024 + col4);
        __half hx = __float2half(w.x), hy = __float2half(w.y);
        __half hz = __float2half(w.z), hw = __float2half(w.w);
        uint2 hi;
        { __half2 p0 = __halves2half2(hx, hy), p1 = __halves2half2(hz, hw);
          hi.x = *(uint32_t*)&p0; hi.y = *(uint32_t*)&p1; }
        uint2 lo = pack4h(w.x - __half2float(hx), w.y - __half2float(hy),
                          w.z - __half2float(hz), w.w - __half2float(hw));
        *(uint2*)(g_WW + (size_t)row * 2048 + col4) = hi;
        *(uint2*)(g_WW + (size_t)row * 2048 + 1024 + col4) = lo;
    }
}

// W_ih -> single fp16 (vectorized)
__global__ void build_Wih_kernel(const float* __restrict__ W_ih) {
    int i = blockIdx.x * blockDim.x + threadIdx.x;
    if (i < G_ * D_ / 4) {
        int row = i >> 8;
        int col4 = (i & 255) * 4;
        float4 w = *(const float4*)(W_ih + (size_t)row * 1024 + col4);
        *(uint2*)(g_Wih + (size_t)row * 1024 + col4) = pack4h(w.x, w.y, w.z, w.w);
    }
}

// feature [b][t][d] -> fp16, rows m = t*64+b (vectorized)
__global__ void build_fA_kernel(const float* __restrict__ feature) {
    int i = blockIdx.x * blockDim.x + threadIdx.x;
    if (i < T_ * B_ * D_ / 4) {
        int k4 = (i & 255) * 4;
        int m = i >> 8;
        int tt = m >> 6, b = m & 63;
        float4 v = *(const float4*)(feature + ((size_t)b * T_ + tt) * D_ + k4);
        *(uint2*)(g_fh + (size_t)m * 1024 + k4) = pack4h(v.x, v.y, v.z, v.w);
    }
}

// ---------------- Phase A: x_gates GEMM via HMMA fp16 (single-pass W) ---------
static constexpr uint32_t XS_AH = 0;        // 16KB
static constexpr uint32_t XS_BH = 16384;    // 16KB
static constexpr uint32_t XS_STAGE = 32768;
static constexpr uint32_t XS_REQ = 2 * XS_STAGE + 1024;

__global__ __launch_bounds__(256, 1) void gemm_xg_tc(
    const float* __restrict__ b_ih, const float* __restrict__ b_hh)
{
    extern __shared__ char dsm_raw[];
    uint32_t raw = smem_to_u32(dsm_raw);
    uint32_t sbase = (raw + 1023u) & ~1023u;
    char* sm = dsm_raw + (sbase - raw);

    int tid = threadIdx.x;
    int wid = tid >> 5, lane = tid & 31;
    int m0 = blockIdx.x * 128;
    int n0 = blockIdx.y * 128;
    int wm = wid >> 1, wn = wid & 1;

    int q8 = lane >> 3, r8 = lane & 7;
    uint32_t a_lrow = (uint32_t)(r8 + (q8 & 1) * 8);
    uint32_t a_kb   = (uint32_t)((q8 >> 1) * 16);
    uint32_t b_lrow = (uint32_t)(r8 + (q8 >> 1) * 8);
    uint32_t b_kb   = (uint32_t)((q8 & 1) * 16);

    int srow = tid >> 3;
    int colB = (tid & 7) * 8;

    int r4 = lane >> 2, c4 = lane & 3;
    float2 bias2[8];
#pragma unroll
    for (int nt = 0; nt < 8; nt++) {
        int n = n0 + wn * 64 + nt * 8 + c4 * 2;
        bias2[nt] = make_float2(b_ih[n] + b_hh[n], b_ih[n + 1] + b_hh[n + 1]);
    }

    float acc[2][8][4];
#pragma unroll
    for (int mt = 0; mt < 2; mt++)
#pragma unroll
        for (int nt = 0; nt < 8; nt++)
#pragma unroll
            for (int i = 0; i < 4; i++) acc[mt][nt][i] = 0.f;

    {
#pragma unroll
        for (int i = 0; i < 4; i++) {
            int r = srow + 32 * i;
            uint32_t d = SWZ((uint32_t)(r * 128 + colB * 2));
            cp_async16(sbase + XS_AH + d, g_fh + (size_t)(m0 + r) * 1024 + colB);
            cp_async16(sbase + XS_BH + d, g_Wih + (size_t)(n0 + r) * 1024 + colB);
        }
        CP_COMMIT();
    }

#pragma unroll 1
    for (int c = 0; c < 16; c++) {
        uint32_t sb = sbase + (c & 1) * XS_STAGE;
        CP_WAIT(0);
        __syncthreads();
        if (c < 15) {
            int kc = (c + 1) * 64;
            uint32_t nb = (c & 1) ? 0u : XS_STAGE;
#pragma unroll
            for (int i = 0; i < 4; i++) {
                int r = srow + 32 * i;
                uint32_t d = nb + SWZ((uint32_t)(r * 128 + colB * 2));
                cp_async16(sbase + XS_AH + d, g_fh + (size_t)(m0 + r) * 1024 + kc + colB);
                cp_async16(sbase + XS_BH + d, g_Wih + (size_t)(n0 + r) * 1024 + kc + colB);
            }
            CP_COMMIT();
        }

#pragma unroll
        for (int kk = 0; kk < 4; kk++) {
            uint32_t koff = (uint32_t)(kk * 32) + a_kb;
            uint32_t kboff = (uint32_t)(kk * 32) + b_kb;
            uint32_t Ah[2][4], Bh[4][4];
#pragma unroll
            for (int mt = 0; mt < 2; mt++) {
                uint32_t rbase = (uint32_t)((wm * 32 + mt * 16 + a_lrow) * 128);
                ldsm_x4(Ah[mt][0], Ah[mt][1], Ah[mt][2], Ah[mt][3],
                        sb + XS_AH + SWZ(rbase + koff));
            }
#pragma unroll
            for (int ng = 0; ng < 4; ng++) {
                uint32_t rbase = (uint32_t)((wn * 64 + ng * 16 + b_lrow) * 128);
                ldsm_x4(Bh[ng][0], Bh[ng][1], Bh[ng][2], Bh[ng][3],
                        sb + XS_BH + SWZ(rbase + kboff));
            }
#pragma unroll
            for (int mt = 0; mt < 2; mt++)
#pragma unroll
                for (int ng = 0; ng < 4; ng++) {
                    hmma16816(acc[mt][ng * 2],     Ah[mt][0], Ah[mt][1], Ah[mt][2], Ah[mt][3], Bh[ng][0], Bh[ng][1]);
                    hmma16816(acc[mt][ng * 2 + 1], Ah[mt][0], Ah[mt][1], Ah[mt][2], Ah[mt][3], Bh[ng][2], Bh[ng][3]);
                }
        }
    }

#pragma unroll
    for (int mt = 0; mt < 2; mt++) {
        int row0 = m0 + wm * 32 + mt * 16 + r4;
#pragma unroll
        for (int nt = 0; nt < 8; nt++) {
            int n = n0 + wn * 64 + nt * 8 + c4 * 2;
            *(float2*)(g_xg + (size_t)row0 * G_ + n) =
                make_float2(acc[mt][nt][0] + bias2[nt].x, acc[mt][nt][1] + bias2[nt].y);
            *(float2*)(g_xg + (size_t)(row0 + 8) * G_ + n) =
                make_float2(acc[mt][nt][2] + bias2[nt].x, acc[mt][nt][3] + bias2[nt].y);
        }
    }
}

// ---------------- Phase B: persistent recurrence (fp16 h, 2-pass W) -----------
static constexpr uint32_t OFF_A0  = 0;          // 32KB stage buf 0
static constexpr uint32_t OFF_A1  = 32768;      // 32KB stage buf 1
static constexpr uint32_t OFF_WLO = 65536;      // 64KB resident W_lo
static constexpr uint32_t OFF_MB  = 131072;     // 2 mbarriers
static constexpr uint32_t OFF_S   = 131136;     // ssum [8][64][34] f32
static constexpr uint32_t SMEM_USED = OFF_S + 8 * 64 * 34 * 4;
static constexpr uint32_t SMEM_REQ  = SMEM_USED + 1024;

__global__ __launch_bounds__(256, 1) void lstm_persistent(
    const int* __restrict__ seq_len, float* __restrict__ out)
{
    extern __shared__ char dsm_raw[];
    uint32_t raw = smem_to_u32(dsm_raw);
    uint32_t sbase = (raw + 1023u) & ~1023u;
    char* sm = dsm_raw + (sbase - raw);

    int tid = threadIdx.x;
    int wid = tid >> 5, lane = tid & 31;
    int bx = blockIdx.x;
    int j0 = bx * 8;
    int grp = bx >> 5;

    int q8 = lane >> 3, r8 = lane & 7;
    uint32_t a_lrow = (uint32_t)(r8 + (q8 & 1) * 8);
    uint32_t a_kb   = (uint32_t)((q8 >> 1) * 16);
    uint32_t b_lrow = (uint32_t)(r8 + (q8 >> 1) * 8);
    uint32_t b_kb   = (uint32_t)((q8 & 1) * 16);

    if (tid == 0) {
        MBARRIER_INIT(sbase + OFF_MB, 1);
        MBARRIER_INIT(sbase + OFF_MB + 8, 1);
    }

    int sg[4];
#pragma unroll
    for (int i = 0; i < 4; i++) sg[i] = (grp + 1 + i) & 3;

    // ---- load W_hi into WLO temp, ldsm to regs; then load W_lo resident ----
    uint32_t wr[4][2][4][2];
    {
        int rr = tid >> 3;
        int cb = (tid & 7) * 8;
        int gn = (rr >> 3) * H_ + j0 + (rr & 7);
        const __half* wrow = g_WW + (size_t)gn * 2048;
#pragma unroll
        for (int it = 0; it < 16; it++) {
            int col = it * 64 + cb;
            uint32_t soff = (uint32_t)((col >> 6) * 4096) +
                            SWZ((uint32_t)(rr * 128 + (col & 63) * 2));
            *(uint4*)(sm + OFF_WLO + soff) = *(const uint4*)(wrow + col);   // hi (temp)
        }
        __syncthreads();
#pragma unroll
        for (int i = 0; i < 4; i++)
#pragma unroll
            for (int kk = 0; kk < 2; kk++) {
                int scol = sg[i] * 256 + wid * 32 + kk * 16;
                uint32_t sub = (uint32_t)((scol >> 6) * 4096);
                uint32_t cin2 = (uint32_t)((scol & 63) * 2) + b_kb;
                ldsm_x4(wr[i][kk][0][0], wr[i][kk][0][1],
                        wr[i][kk][1][0], wr[i][kk][1][1],
                        sbase + OFF_WLO + sub + SWZ(b_lrow * 128 + cin2));
                ldsm_x4(wr[i][kk][2][0], wr[i][kk][2][1],
                        wr[i][kk][3][0], wr[i][kk][3][1],
                        sbase + OFF_WLO + sub + SWZ((b_lrow + 16) * 128 + cin2));
            }
        __syncthreads();
#pragma unroll
        for (int it = 0; it < 16; it++) {
            int col = it * 64 + cb;
            uint32_t soff = (uint32_t)((col >> 6) * 4096) +
                            SWZ((uint32_t)(rr * 128 + (col & 63) * 2));
            *(uint4*)(sm + OFF_WLO + soff) = *(const uint4*)(wrow + 1024 + col);  // lo
        }
        __syncthreads();
    }

    // per-warp A ldsm constants (subtile = 8KB: 64 rows x 64 cols)
    uint32_t asub0 = (uint32_t)(((wid * 32) >> 6) * 8192);
    uint32_t acin0 = (uint32_t)(((wid * 32) & 63) * 2) + a_kb;
    uint32_t asub1 = (uint32_t)(((wid * 32 + 16) >> 6) * 8192);
    uint32_t acin1 = (uint32_t)(((wid * 32 + 16) & 63) * 2) + a_kb;

    int eb0 = tid >> 3;
    int eb1 = eb0 + 32;
    int eu = tid & 7;
    int ej = j0 + eu;
    int sl0 = seq_len[eb0], sl1 = seq_len[eb1];
    float c0 = 0.f, c1 = 0.f;
    int hs = ej >> 8, hsub = (ej >> 6) & 3, hcin = ej & 63;
    uint32_t hbase = (uint32_t)((hs * 4 + hsub) * 8192);
    uint32_t hoff0 = hbase + SWZ((uint32_t)(eb0 * 128 + hcin * 2));
    uint32_t hoff1 = hbase + SWZ((uint32_t)(eb1 * 128 + hcin * 2));

    float* ssum = (float*)(sm + OFF_S);
    volatile unsigned* prod = (volatile unsigned*)g_prod;
    volatile unsigned* cons = (volatile unsigned*)&g_cons;
    uint32_t done0 = 0, done1 = 0;

    __syncthreads();

#pragma unroll 1
    for (int t = 0; t < T_; t++) {
        const uint8_t* __restrict__ hin2 = g_hh2[t & 1];
        uint8_t* __restrict__ hout2 = g_hh2[(t + 1) & 1];
        unsigned needp = 32u * (unsigned)t;

        if (tid == 0) {
            while (prod[sg[0]] < needp) { }
            MBARRIER_EXPECT_TX(sbase + OFF_MB, 32768);
            cp_bulk_g2s(sbase + OFF_A0, hin2 + sg[0] * 32768, 32768, sbase + OFF_MB);
            while (prod[sg[1]] < needp) { }
            MBARRIER_EXPECT_TX(sbase + OFF_MB + 8, 32768);
            cp_bulk_g2s(sbase + OFF_A1, hin2 + sg[1] * 32768, 32768, sbase + OFF_MB + 8);
        }

        float xr0[4], xr1[4];
        {
            const float* xa = g_xg + ((size_t)t * B_ + eb0) * G_ + ej;
            const float* xb = g_xg + ((size_t)t * B_ + eb1) * G_ + ej;
#pragma unroll
            for (int g4 = 0; g4 < 4; g4++) { xr0[g4] = xa[g4 * H_]; xr1[g4] = xb[g4 * H_]; }
        }

        float acc[4][4][4];
#pragma unroll
        for (int mt = 0; mt < 4; mt++)
#pragma unroll
            for (int nt = 0; nt < 4; nt++)
#pragma unroll
                for (int i = 0; i < 4; i++) acc[mt][nt][i] = 0.f;

#pragma unroll
        for (int i = 0; i < 4; i++) {
            uint32_t abuf = (i & 1) ? OFF_A1 : OFF_A0;
            if (i & 1) { MBARRIER_WAIT_PARITY(sbase + OFF_MB + 8, done1 & 1); done1++; }
            else       { MBARRIER_WAIT_PARITY(sbase + OFF_MB,     done0 & 1); done0++; }
            if (i == 3 && tid == 0) atomicAdd(&g_cons, 1u);

#pragma unroll
            for (int kk = 0; kk < 2; kk++) {
                uint32_t atile = sbase + abuf + (kk ? asub1 : asub0);
                uint32_t cin2  = kk ? acin1 : acin0;
                int scol = sg[i] * 256 + wid * 32 + kk * 16;
                uint32_t wsub = (uint32_t)((scol >> 6) * 4096);
                uint32_t wcin2 = (uint32_t)((scol & 63) * 2) + b_kb;

                uint32_t ah[4][4];
#pragma unroll
                for (int mt = 0; mt < 4; mt++)
                    ldsm_x4(ah[mt][0], ah[mt][1], ah[mt][2], ah[mt][3],
                            atile + SWZ((mt * 16 + a_lrow) * 128 + cin2));
                uint32_t wl[4][2];
                ldsm_x4(wl[0][0], wl[0][1], wl[1][0], wl[1][1],
                        sbase + OFF_WLO + wsub + SWZ(b_lrow * 128 + wcin2));
                ldsm_x4(wl[2][0], wl[2][1], wl[3][0], wl[3][1],
                        sbase + OFF_WLO + wsub + SWZ((b_lrow + 16) * 128 + wcin2));
#pragma unroll
                for (int mt = 0; mt < 4; mt++)
#pragma unroll
                    for (int nt = 0; nt < 4; nt++)
                        hmma16816(acc[mt][nt], ah[mt][0], ah[mt][1], ah[mt][2], ah[mt][3],
                                  wr[i][kk][nt][0], wr[i][kk][nt][1]);
#pragma unroll
                for (int mt = 0; mt < 4; mt++)
#pragma unroll
                    for (int nt = 0; nt < 4; nt++)
                        hmma16816(acc[mt][nt], ah[mt][0], ah[mt][1], ah[mt][2], ah[mt][3],
                                  wl[nt][0], wl[nt][1]);
            }
            __syncthreads();
            if (i < 2 && tid == 0) {
                while (prod[sg[i + 2]] < needp) { }
                uint32_t mb = sbase + OFF_MB + (i & 1) * 8;
                MBARRIER_EXPECT_TX(mb, 32768);
                cp_bulk_g2s(sbase + abuf, hin2 + sg[i + 2] * 32768, 32768, mb);
            }
        }

        {
            int r = lane >> 2, c4 = lane & 3;
            float* pp = ssum + wid * (64 * 34);
#pragma unroll
            for (int mt = 0; mt < 4; mt++)
#pragma unroll
                for (int nt = 0; nt < 4; nt++) {
                    int b1 = mt * 16 + r, n = nt * 8 + c4 * 2;
                    *(float2*)(pp + b1 * 34 + n) =
                        make_float2(acc[mt][nt][0], acc[mt][nt][1]);
                    *(float2*)(pp + (b1 + 8) * 34 + n) =
                        make_float2(acc[mt][nt][2], acc[mt][nt][3]);
                }
        }
        __syncthreads();

        if (tid == 0) {
            unsigned needc = 128u * (unsigned)t;
            while (*cons < needc) { }
        }
        __syncthreads();

        // ---- epilogue: compute + h store, publish, then out stores ----
        float hn_s[2];
#pragma unroll
        for (int it = 0; it < 2; it++) {
            int b = it ? eb1 : eb0;
            float gate[4];
#pragma unroll
            for (int g4 = 0; g4 < 4; g4++) {
                int n = g4 * 8 + eu;
                float s0 = 0.f;
#pragma unroll
                for (int w = 0; w < 8; w++)
                    s0 += ssum[w * (64 * 34) + b * 34 + n];
                gate[g4] = s0 + (it ? xr1[g4] : xr0[g4]);
            }
            float si = sigf(gate[0]);
            float sf = sigf(gate[1]);
            float tg = tanh_fast(gate[2]);
            float so = sigf(gate[3]);
            float cn = fmaf(sf, it ? c1 : c0, si * tg);
            if (it) c1 = cn; else c0 = cn;
            float hn = so * tanh_fast(cn);
            hn_s[it] = hn;
            *(__half*)(hout2 + (it ? hoff1 : hoff0)) = __float2half(hn);
        }

        __threadfence();
        __syncthreads();
        if (tid == 0) atomicAdd(&g_prod[grp], 1u);

        out[((size_t)eb0 * T_ + t) * H_ + ej] = (t < sl0) ? hn_s[0] : 0.f;
        out[((size_t)eb1 * T_ + t) * H_ + ej] = (t < sl1) ? hn_s[1] : 0.f;
    }
}

extern "C" void kernel_launch(void* const* d_in, const int* in_sizes, int n_in,
                              void* d_out, int out_size)
{
    const float* feature = (const float*)d_in[0];
    const float* W_ih    = (const float*)d_in[1];
    const float* W_hh    = (const float*)d_in[2];
    const float* b_ih    = (const float*)d_in[3];
    const float* b_hh    = (const float*)d_in[4];
    const int*   seq_len = (const int*)d_in[5];
    float* out = (float*)d_out;

    cudaFuncSetAttribute(lstm_persistent, cudaFuncAttributeMaxDynamicSharedMemorySize,
                         SMEM_REQ);
    cudaFuncSetAttribute(gemm_xg_tc, cudaFuncAttributeMaxDynamicSharedMemorySize,
                         XS_REQ);

    init_state_kernel<<<(65536 + 255) / 256, 256>>>();
    build_WW_kernel<<<(G_ * H_ / 4 + 255) / 256, 256>>>(W_hh);
    build_Wih_kernel<<<(G_ * D_ / 4 + 255) / 256, 256>>>(W_ih);
    build_fA_kernel<<<(T_ * B_ * D_ / 4 + 255) / 256, 256>>>(feature);
    gemm_xg_tc<<<dim3(256, 32), 256, XS_REQ>>>(b_ih, b_hh);
    lstm_persistent<<<128, 256, SMEM_REQ>>>(seq_len, out);
}

// round 16
// speedup vs baseline: 3.8202x; 1.0880x over previous
#include <cuda_runtime.h>
#include <cuda_fp16.h>
#include <math.h>
#include <stdint.h>

#define B_ 64
#define T_ 512
#define D_ 1024
#define H_ 1024
#define G_ 4096

// ---------------- device scratch (allocation-free rule) ----------------
__device__ float g_xg[(size_t)T_ * B_ * G_];            // [T][B][4H] pre-activations
// h ping-pong as SW128-swizzled image: [pp][stage][sub][64 rows][128B] = 128KB each
__device__ __align__(128) uint8_t g_hh2[2][4 * 4 * 64 * 128];
__device__ __half g_WW[(size_t)G_ * H_];                // W_hh fp16 single-pass
__device__ __half g_Wih[(size_t)G_ * D_];               // W_ih fp16 single-pass
__device__ __half g_fh[(size_t)T_ * B_ * D_];           // feature fp16, rows m = t*64+b
__device__ unsigned g_prod[4];                          // per-group producer counters
__device__ unsigned g_cons;                             // consumption counter

#define SWZ(off) ((off) ^ (((off) >> 3) & 0x70))

__device__ __forceinline__ uint32_t smem_to_u32(const void* p) {
    uint32_t a;
    asm("{ .reg .u64 t; cvta.to.shared.u64 t, %1; cvt.u32.u64 %0, t; }" : "=r"(a) : "l"(p));
    return a;
}

__device__ __forceinline__ void ldsm_x4(uint32_t& r0, uint32_t& r1, uint32_t& r2,
                                        uint32_t& r3, uint32_t addr) {
    asm volatile("ldmatrix.sync.aligned.m8n8.x4.shared.b16 {%0,%1,%2,%3}, [%4];"
                 : "=r"(r0), "=r"(r1), "=r"(r2), "=r"(r3) : "r"(addr));
}

__device__ __forceinline__ void hmma16816(float* d, uint32_t a0, uint32_t a1,
                                          uint32_t a2, uint32_t a3,
                                          uint32_t b0, uint32_t b1) {
    asm volatile(
        "mma.sync.aligned.m16n8k16.row.col.f32.f16.f16.f32 "
        "{%0,%1,%2,%3}, {%4,%5,%6,%7}, {%8,%9}, {%0,%1,%2,%3};"
        : "+f"(d[0]), "+f"(d[1]), "+f"(d[2]), "+f"(d[3])
        : "r"(a0), "r"(a1), "r"(a2), "r"(a3), "r"(b0), "r"(b1));
}

__device__ __forceinline__ void cp_async16(uint32_t dst, const void* src) {
    asm volatile("cp.async.cg.shared.global [%0], [%1], 16;"
                 :: "r"(dst), "l"(src) : "memory");
}
#define CP_COMMIT() asm volatile("cp.async.commit_group;" ::: "memory")
#define CP_WAIT(N)  asm volatile("cp.async.wait_group %0;" :: "n"(N) : "memory")

__device__ __forceinline__ void cp_bulk_g2s(uint32_t dst, const void* src,
                                            uint32_t bytes, uint32_t mbar) {
    asm volatile(
        "cp.async.bulk.shared::cta.global.mbarrier::complete_tx::bytes [%0], [%1], %2, [%3];"
        :: "r"(dst), "l"(src), "r"(bytes), "r"(mbar) : "memory");
}
#define MBARRIER_INIT(addr, cnt) \
    asm volatile("mbarrier.init.shared.b64 [%0], %1;" :: "r"((uint32_t)(addr)), "r"((uint32_t)(cnt)) : "memory")
#define MBARRIER_EXPECT_TX(addr, bytes) \
    asm volatile("mbarrier.arrive.expect_tx.shared.b64 _, [%0], %1;" \
        :: "r"((uint32_t)(addr)), "r"((uint32_t)(bytes)) : "memory")
#define MBARRIER_WAIT_PARITY(mbar_smem_addr, phase_parity) do { \
    uint32_t _mbar = (uint32_t)(mbar_smem_addr); \
    uint32_t _parity = (uint32_t)(phase_parity); \
    uint32_t _done; \
    asm volatile( \
        "{\n\t.reg .pred p;\n\t" \
        "mbarrier.try_wait.parity.acquire.cta.shared::cta.b64 p, [%1], %2;\n\t" \
        "selp.b32 %0, 1, 0, p;\n\t}" \
        : "=r"(_done) : "r"(_mbar), "r"(_parity) : "memory"); \
    if (!_done) { \
        asm volatile( \
            "{\n\t.reg .pred P1;\n\t" \
            "WAIT_LOOP_%=:\n\t" \
            "mbarrier.try_wait.parity.acquire.cta.shared::cta.b64 P1, [%0], %1, 0x989680;\n\t" \
            "@P1 bra.uni WAIT_DONE_%=;\n\t" \
            "bra.uni WAIT_LOOP_%=;\n\t" \
            "WAIT_DONE_%=:\n\t}" \
            :: "r"(_mbar), "r"(_parity) : "memory"); \
    } \
} while(0)

__device__ __forceinline__ float sigf(float x) {
    return __fdividef(1.f, 1.f + __expf(-x));
}
__device__ __forceinline__ float tanh_fast(float x) {
    x = fminf(fmaxf(x, -15.f), 15.f);
    float e = __expf(2.f * x);
    return __fdividef(e - 1.f, e + 1.f);
}

__device__ __forceinline__ uint2 pack4h(float a, float b, float c, float d) {
    __half2 p0 = __floats2half2_rn(a, b);
    __half2 p1 = __floats2half2_rn(c, d);
    uint2 r;
    r.x = *(uint32_t*)&p0;
    r.y = *(uint32_t*)&p1;
    return r;
}

// ---------------- init / prep kernels ----------------
__global__ void init_state_kernel() {
    int i = blockIdx.x * blockDim.x + threadIdx.x;
    if (i < 65536) ((uint32_t*)g_hh2)[i] = 0u;   // 2 x 128KB
    if (i < 4) g_prod[i] = 0u;
    if (i == 4) g_cons = 0u;
}

// W_hh -> single fp16 (vectorized: 4 cols/thread)
__global__ void build_WW_kernel(const float* __restrict__ W_hh) {
    int i = blockIdx.x * blockDim.x + threadIdx.x;
    if (i < G_ * H_ / 4) {
        int row = i >> 8;
        int col4 = (i & 255) * 4;
        float4 w = *(const float4*)(W_hh + (size_t)row * 1024 + col4);
        *(uint2*)(g_WW + (size_t)row * 1024 + col4) = pack4h(w.x, w.y, w.z, w.w);
    }
}

// W_ih -> single fp16 (vectorized)
__global__ void build_Wih_kernel(const float* __restrict__ W_ih) {
    int i = blockIdx.x * blockDim.x + threadIdx.x;
    if (i < G_ * D_ / 4) {
        int row = i >> 8;
        int col4 = (i & 255) * 4;
        float4 w = *(const float4*)(W_ih + (size_t)row * 1024 + col4);
        *(uint2*)(g_Wih + (size_t)row * 1024 + col4) = pack4h(w.x, w.y, w.z, w.w);
    }
}

// feature [b][t][d] -> fp16, rows m = t*64+b (vectorized)
__global__ void build_fA_kernel(const float* __restrict__ feature) {
    int i = blockIdx.x * blockDim.x + threadIdx.x;
    if (i < T_ * B_ * D_ / 4) {
        int k4 = (i & 255) * 4;
        int m = i >> 8;
        int tt = m >> 6, b = m & 63;
        float4 v = *(const float4*)(feature + ((size_t)b * T_ + tt) * D_ + k4);
        *(uint2*)(g_fh + (size_t)m * 1024 + k4) = pack4h(v.x, v.y, v.z, v.w);
    }
}

// ---------------- Phase A: x_gates GEMM via HMMA fp16 (single-pass W) ---------
static constexpr uint32_t XS_AH = 0;        // 16KB
static constexpr uint32_t XS_BH = 16384;    // 16KB
static constexpr uint32_t XS_STAGE = 32768;
static constexpr uint32_t XS_REQ = 2 * XS_STAGE + 1024;

__global__ __launch_bounds__(256, 1) void gemm_xg_tc(
    const float* __restrict__ b_ih, const float* __restrict__ b_hh)
{
    extern __shared__ char dsm_raw[];
    uint32_t raw = smem_to_u32(dsm_raw);
    uint32_t sbase = (raw + 1023u) & ~1023u;
    char* sm = dsm_raw + (sbase - raw);

    int tid = threadIdx.x;
    int wid = tid >> 5, lane = tid & 31;
    int m0 = blockIdx.x * 128;
    int n0 = blockIdx.y * 128;
    int wm = wid >> 1, wn = wid & 1;

    int q8 = lane >> 3, r8 = lane & 7;
    uint32_t a_lrow = (uint32_t)(r8 + (q8 & 1) * 8);
    uint32_t a_kb   = (uint32_t)((q8 >> 1) * 16);
    uint32_t b_lrow = (uint32_t)(r8 + (q8 >> 1) * 8);
    uint32_t b_kb   = (uint32_t)((q8 & 1) * 16);

    int srow = tid >> 3;
    int colB = (tid & 7) * 8;

    int r4 = lane >> 2, c4 = lane & 3;
    float2 bias2[8];
#pragma unroll
    for (int nt = 0; nt < 8; nt++) {
        int n = n0 + wn * 64 + nt * 8 + c4 * 2;
        bias2[nt] = make_float2(b_ih[n] + b_hh[n], b_ih[n + 1] + b_hh[n + 1]);
    }

    float acc[2][8][4];
#pragma unroll
    for (int mt = 0; mt < 2; mt++)
#pragma unroll
        for (int nt = 0; nt < 8; nt++)
#pragma unroll
            for (int i = 0; i < 4; i++) acc[mt][nt][i] = 0.f;

    {
#pragma unroll
        for (int i = 0; i < 4; i++) {
            int r = srow + 32 * i;
            uint32_t d = SWZ((uint32_t)(r * 128 + colB * 2));
            cp_async16(sbase + XS_AH + d, g_fh + (size_t)(m0 + r) * 1024 + colB);
            cp_async16(sbase + XS_BH + d, g_Wih + (size_t)(n0 + r) * 1024 + colB);
        }
        CP_COMMIT();
    }

#pragma unroll 1
    for (int c = 0; c < 16; c++) {
        uint32_t sb = sbase + (c & 1) * XS_STAGE;
        CP_WAIT(0);
        __syncthreads();
        if (c < 15) {
            int kc = (c + 1) * 64;
            uint32_t nb = (c & 1) ? 0u : XS_STAGE;
#pragma unroll
            for (int i = 0; i < 4; i++) {
                int r = srow + 32 * i;
                uint32_t d = nb + SWZ((uint32_t)(r * 128 + colB * 2));
                cp_async16(sbase + XS_AH + d, g_fh + (size_t)(m0 + r) * 1024 + kc + colB);
                cp_async16(sbase + XS_BH + d, g_Wih + (size_t)(n0 + r) * 1024 + kc + colB);
            }
            CP_COMMIT();
        }

#pragma unroll
        for (int kk = 0; kk < 4; kk++) {
            uint32_t koff = (uint32_t)(kk * 32) + a_kb;
            uint32_t kboff = (uint32_t)(kk * 32) + b_kb;
            uint32_t Ah[2][4], Bh[4][4];
#pragma unroll
            for (int mt = 0; mt < 2; mt++) {
                uint32_t rbase = (uint32_t)((wm * 32 + mt * 16 + a_lrow) * 128);
                ldsm_x4(Ah[mt][0], Ah[mt][1], Ah[mt][2], Ah[mt][3],
                        sb + XS_AH + SWZ(rbase + koff));
            }
#pragma unroll
            for (int ng = 0; ng < 4; ng++) {
                uint32_t rbase = (uint32_t)((wn * 64 + ng * 16 + b_lrow) * 128);
                ldsm_x4(Bh[ng][0], Bh[ng][1], Bh[ng][2], Bh[ng][3],
                        sb + XS_BH + SWZ(rbase + kboff));
            }
#pragma unroll
            for (int mt = 0; mt < 2; mt++)
#pragma unroll
                for (int ng = 0; ng < 4; ng++) {
                    hmma16816(acc[mt][ng * 2],     Ah[mt][0], Ah[mt][1], Ah[mt][2], Ah[mt][3], Bh[ng][0], Bh[ng][1]);
                    hmma16816(acc[mt][ng * 2 + 1], Ah[mt][0], Ah[mt][1], Ah[mt][2], Ah[mt][3], Bh[ng][2], Bh[ng][3]);
                }
        }
    }

#pragma unroll
    for (int mt = 0; mt < 2; mt++) {
        int row0 = m0 + wm * 32 + mt * 16 + r4;
#pragma unroll
        for (int nt = 0; nt < 8; nt++) {
            int n = n0 + wn * 64 + nt * 8 + c4 * 2;
            *(float2*)(g_xg + (size_t)row0 * G_ + n) =
                make_float2(acc[mt][nt][0] + bias2[nt].x, acc[mt][nt][1] + bias2[nt].y);
            *(float2*)(g_xg + (size_t)(row0 + 8) * G_ + n) =
                make_float2(acc[mt][nt][2] + bias2[nt].x, acc[mt][nt][3] + bias2[nt].y);
        }
    }
}

// ---------------- Phase B: persistent recurrence (fp16 h, single-pass W) ------
static constexpr uint32_t OFF_A0  = 0;          // 32KB stage buf 0
static constexpr uint32_t OFF_A1  = 32768;      // 32KB stage buf 1
static constexpr uint32_t OFF_WST = 65536;      // 64KB W staging (transient)
static constexpr uint32_t OFF_MB  = 131072;     // 2 mbarriers
static constexpr uint32_t OFF_S   = 131136;     // ssum [8][64][34] f32
static constexpr uint32_t SMEM_USED = OFF_S + 8 * 64 * 34 * 4;
static constexpr uint32_t SMEM_REQ  = SMEM_USED + 1024;

__global__ __launch_bounds__(256, 1) void lstm_persistent(
    const int* __restrict__ seq_len, float* __restrict__ out)
{
    extern __shared__ char dsm_raw[];
    uint32_t raw = smem_to_u32(dsm_raw);
    uint32_t sbase = (raw + 1023u) & ~1023u;
    char* sm = dsm_raw + (sbase - raw);

    int tid = threadIdx.x;
    int wid = tid >> 5, lane = tid & 31;
    int bx = blockIdx.x;
    int j0 = bx * 8;
    int grp = bx >> 5;

    int q8 = lane >> 3, r8 = lane & 7;
    uint32_t a_lrow = (uint32_t)(r8 + (q8 & 1) * 8);
    uint32_t a_kb   = (uint32_t)((q8 >> 1) * 16);
    uint32_t b_lrow = (uint32_t)(r8 + (q8 >> 1) * 8);
    uint32_t b_kb   = (uint32_t)((q8 & 1) * 16);

    if (tid == 0) {
        MBARRIER_INIT(sbase + OFF_MB, 1);
        MBARRIER_INIT(sbase + OFF_MB + 8, 1);
    }

    int sg[4];
#pragma unroll
    for (int i = 0; i < 4; i++) sg[i] = (grp + 1 + i) & 3;

    // ---- load W (single fp16) into staging smem, ldsm to regs ----
    uint32_t wr[4][2][4][2];
    {
        int rr = tid >> 3;
        int cb = (tid & 7) * 8;
        int gn = (rr >> 3) * H_ + j0 + (rr & 7);
        const __half* wrow = g_WW + (size_t)gn * 1024;
#pragma unroll
        for (int it = 0; it < 16; it++) {
            int col = it * 64 + cb;
            uint32_t soff = (uint32_t)((col >> 6) * 4096) +
                            SWZ((uint32_t)(rr * 128 + (col & 63) * 2));
            *(uint4*)(sm + OFF_WST + soff) = *(const uint4*)(wrow + col);
        }
        __syncthreads();
#pragma unroll
        for (int i = 0; i < 4; i++)
#pragma unroll
            for (int kk = 0; kk < 2; kk++) {
                int scol = sg[i] * 256 + wid * 32 + kk * 16;
                uint32_t sub = (uint32_t)((scol >> 6) * 4096);
                uint32_t cin2 = (uint32_t)((scol & 63) * 2) + b_kb;
                ldsm_x4(wr[i][kk][0][0], wr[i][kk][0][1],
                        wr[i][kk][1][0], wr[i][kk][1][1],
                        sbase + OFF_WST + sub + SWZ(b_lrow * 128 + cin2));
                ldsm_x4(wr[i][kk][2][0], wr[i][kk][2][1],
                        wr[i][kk][3][0], wr[i][kk][3][1],
                        sbase + OFF_WST + sub + SWZ((b_lrow + 16) * 128 + cin2));
            }
        __syncthreads();
    }

    // per-warp A ldsm constants (subtile = 8KB: 64 rows x 64 cols)
    uint32_t asub0 = (uint32_t)(((wid * 32) >> 6) * 8192);
    uint32_t acin0 = (uint32_t)(((wid * 32) & 63) * 2) + a_kb;
    uint32_t asub1 = (uint32_t)(((wid * 32 + 16) >> 6) * 8192);
    uint32_t acin1 = (uint32_t)(((wid * 32 + 16) & 63) * 2) + a_kb;

    int eb0 = tid >> 3;
    int eb1 = eb0 + 32;
    int eu = tid & 7;
    int ej = j0 + eu;
    int sl0 = seq_len[eb0], sl1 = seq_len[eb1];
    float c0 = 0.f, c1 = 0.f;
    int hs = ej >> 8, hsub = (ej >> 6) & 3, hcin = ej & 63;
    uint32_t hbase = (uint32_t)((hs * 4 + hsub) * 8192);
    uint32_t hoff0 = hbase + SWZ((uint32_t)(eb0 * 128 + hcin * 2));
    uint32_t hoff1 = hbase + SWZ((uint32_t)(eb1 * 128 + hcin * 2));

    float* ssum = (float*)(sm + OFF_S);
    volatile unsigned* prod = (volatile unsigned*)g_prod;
    volatile unsigned* cons = (volatile unsigned*)&g_cons;
    uint32_t done0 = 0, done1 = 0;

    __syncthreads();

#pragma unroll 1
    for (int t = 0; t < T_; t++) {
        const uint8_t* __restrict__ hin2 = g_hh2[t & 1];
        uint8_t* __restrict__ hout2 = g_hh2[(t + 1) & 1];
        unsigned needp = 32u * (unsigned)t;

        if (tid == 0) {
            while (prod[sg[0]] < needp) { }
            MBARRIER_EXPECT_TX(sbase + OFF_MB, 32768);
            cp_bulk_g2s(sbase + OFF_A0, hin2 + sg[0] * 32768, 32768, sbase + OFF_MB);
            while (prod[sg[1]] < needp) { }
            MBARRIER_EXPECT_TX(sbase + OFF_MB + 8, 32768);
            cp_bulk_g2s(sbase + OFF_A1, hin2 + sg[1] * 32768, 32768, sbase + OFF_MB + 8);
        }

        float xr0[4], xr1[4];
        {
            const float* xa = g_xg + ((size_t)t * B_ + eb0) * G_ + ej;
            const float* xb = g_xg + ((size_t)t * B_ + eb1) * G_ + ej;
#pragma unroll
            for (int g4 = 0; g4 < 4; g4++) { xr0[g4] = xa[g4 * H_]; xr1[g4] = xb[g4 * H_]; }
        }

        float acc[4][4][4];
#pragma unroll
        for (int mt = 0; mt < 4; mt++)
#pragma unroll
            for (int nt = 0; nt < 4; nt++)
#pragma unroll
                for (int i = 0; i < 4; i++) acc[mt][nt][i] = 0.f;

#pragma unroll
        for (int i = 0; i < 4; i++) {
            uint32_t abuf = (i & 1) ? OFF_A1 : OFF_A0;
            if (i & 1) { MBARRIER_WAIT_PARITY(sbase + OFF_MB + 8, done1 & 1); done1++; }
            else       { MBARRIER_WAIT_PARITY(sbase + OFF_MB,     done0 & 1); done0++; }
            if (i == 3 && tid == 0) atomicAdd(&g_cons, 1u);

#pragma unroll
            for (int kk = 0; kk < 2; kk++) {
                uint32_t atile = sbase + abuf + (kk ? asub1 : asub0);
                uint32_t cin2  = kk ? acin1 : acin0;

                uint32_t ah[4][4];
#pragma unroll
                for (int mt = 0; mt < 4; mt++)
                    ldsm_x4(ah[mt][0], ah[mt][1], ah[mt][2], ah[mt][3],
                            atile + SWZ((mt * 16 + a_lrow) * 128 + cin2));
#pragma unroll
                for (int mt = 0; mt < 4; mt++)
#pragma unroll
                    for (int nt = 0; nt < 4; nt++)
                        hmma16816(acc[mt][nt], ah[mt][0], ah[mt][1], ah[mt][2], ah[mt][3],
                                  wr[i][kk][nt][0], wr[i][kk][nt][1]);
            }
            __syncthreads();
            if (i < 2 && tid == 0) {
                while (prod[sg[i + 2]] < needp) { }
                uint32_t mb = sbase + OFF_MB + (i & 1) * 8;
                MBARRIER_EXPECT_TX(mb, 32768);
                cp_bulk_g2s(sbase + abuf, hin2 + sg[i + 2] * 32768, 32768, mb);
            }
        }

        {
            int r = lane >> 2, c4 = lane & 3;
            float* pp = ssum + wid * (64 * 34);
#pragma unroll
            for (int mt = 0; mt < 4; mt++)
#pragma unroll
                for (int nt = 0; nt < 4; nt++) {
                    int b1 = mt * 16 + r, n = nt * 8 + c4 * 2;
                    *(float2*)(pp + b1 * 34 + n) =
                        make_float2(acc[mt][nt][0], acc[mt][nt][1]);
                    *(float2*)(pp + (b1 + 8) * 34 + n) =
                        make_float2(acc[mt][nt][2], acc[mt][nt][3]);
                }
        }
        __syncthreads();

        if (tid == 0) {
            unsigned needc = 128u * (unsigned)t;
            while (*cons < needc) { }
        }
        __syncthreads();

        // ---- epilogue: compute + h store, publish, then out stores ----
        float hn_s[2];
#pragma unroll
        for (int it = 0; it < 2; it++) {
            int b = it ? eb1 : eb0;
            float gate[4];
#pragma unroll
            for (int g4 = 0; g4 < 4; g4++) {
                int n = g4 * 8 + eu;
                float s0 = 0.f;
#pragma unroll
                for (int w = 0; w < 8; w++)
                    s0 += ssum[w * (64 * 34) + b * 34 + n];
                gate[g4] = s0 + (it ? xr1[g4] : xr0[g4]);
            }
            float si = sigf(gate[0]);
            float sf = sigf(gate[1]);
            float tg = tanh_fast(gate[2]);
            float so = sigf(gate[3]);
            float cn = fmaf(sf, it ? c1 : c0, si * tg);
            if (it) c1 = cn; else c0 = cn;
            float hn = so * tanh_fast(cn);
            hn_s[it] = hn;
            *(__half*)(hout2 + (it ? hoff1 : hoff0)) = __float2half(hn);
        }

        __threadfence();
        __syncthreads();
        if (tid == 0) atomicAdd(&g_prod[grp], 1u);

        out[((size_t)eb0 * T_ + t) * H_ + ej] = (t < sl0) ? hn_s[0] : 0.f;
        out[((size_t)eb1 * T_ + t) * H_ + ej] = (t < sl1) ? hn_s[1] : 0.f;
    }
}

extern "C" void kernel_launch(void* const* d_in, const int* in_sizes, int n_in,
                              void* d_out, int out_size)
{
    const float* feature = (const float*)d_in[0];
    const float* W_ih    = (const float*)d_in[1];
    const float* W_hh    = (const float*)d_in[2];
    const float* b_ih    = (const float*)d_in[3];
    const float* b_hh    = (const float*)d_in[4];
    const int*   seq_len = (const int*)d_in[5];
    float* out = (float*)d_out;

    cudaFuncSetAttribute(lstm_persistent, cudaFuncAttributeMaxDynamicSharedMemorySize,
                         SMEM_REQ);
    cudaFuncSetAttribute(gemm_xg_tc, cudaFuncAttributeMaxDynamicSharedMemorySize,
                         XS_REQ);

    init_state_kernel<<<(65536 + 255) / 256, 256>>>();
    build_WW_kernel<<<(G_ * H_ / 4 + 255) / 256, 256>>>(W_hh);
    build_Wih_kernel<<<(G_ * D_ / 4 + 255) / 256, 256>>>(W_ih);
    build_fA_kernel<<<(T_ * B_ * D_ / 4 + 255) / 256, 256>>>(feature);
    gemm_xg_tc<<<dim3(256, 32), 256, XS_REQ>>>(b_ih, b_hh);
    lstm_persistent<<<128, 256, SMEM_REQ>>>(seq_len, out);
}

// round 17
// speedup vs baseline: 3.8589x; 1.0101x over previous
#include <cuda_runtime.h>
#include <cuda_fp16.h>
#include <math.h>
#include <stdint.h>

#define B_ 64
#define T_ 512
#define D_ 1024
#define H_ 1024
#define G_ 4096

// ---------------- device scratch (allocation-free rule) ----------------
__device__ float g_xg[(size_t)T_ * B_ * G_];            // [T][B][4H] pre-activations
// h ping-pong as SW128-swizzled image: [pp][stage][sub][64 rows][128B] = 128KB each
__device__ __align__(128) uint8_t g_hh2[2][4 * 4 * 64 * 128];
__device__ __half g_WW[(size_t)G_ * H_];                // W_hh fp16 single-pass
__device__ __half g_Wih[(size_t)G_ * D_];               // W_ih fp16 single-pass
__device__ __half g_fh[(size_t)T_ * B_ * D_];           // feature fp16, rows m = t*64+b
__device__ unsigned g_prod[4];                          // per-group producer counters
__device__ unsigned g_cons;                             // consumption counter

#define SWZ(off) ((off) ^ (((off) >> 3) & 0x70))

__device__ __forceinline__ uint32_t smem_to_u32(const void* p) {
    uint32_t a;
    asm("{ .reg .u64 t; cvta.to.shared.u64 t, %1; cvt.u32.u64 %0, t; }" : "=r"(a) : "l"(p));
    return a;
}

__device__ __forceinline__ void ldsm_x4(uint32_t& r0, uint32_t& r1, uint32_t& r2,
                                        uint32_t& r3, uint32_t addr) {
    asm volatile("ldmatrix.sync.aligned.m8n8.x4.shared.b16 {%0,%1,%2,%3}, [%4];"
                 : "=r"(r0), "=r"(r1), "=r"(r2), "=r"(r3) : "r"(addr));
}

__device__ __forceinline__ void hmma16816(float* d, uint32_t a0, uint32_t a1,
                                          uint32_t a2, uint32_t a3,
                                          uint32_t b0, uint32_t b1) {
    asm volatile(
        "mma.sync.aligned.m16n8k16.row.col.f32.f16.f16.f32 "
        "{%0,%1,%2,%3}, {%4,%5,%6,%7}, {%8,%9}, {%0,%1,%2,%3};"
        : "+f"(d[0]), "+f"(d[1]), "+f"(d[2]), "+f"(d[3])
        : "r"(a0), "r"(a1), "r"(a2), "r"(a3), "r"(b0), "r"(b1));
}

__device__ __forceinline__ void cp_async16(uint32_t dst, const void* src) {
    asm volatile("cp.async.cg.shared.global [%0], [%1], 16;"
                 :: "r"(dst), "l"(src) : "memory");
}
#define CP_COMMIT() asm volatile("cp.async.commit_group;" ::: "memory")
#define CP_WAIT(N)  asm volatile("cp.async.wait_group %0;" :: "n"(N) : "memory")

__device__ __forceinline__ void cp_bulk_g2s(uint32_t dst, const void* src,
                                            uint32_t bytes, uint32_t mbar) {
    asm volatile(
        "cp.async.bulk.shared::cta.global.mbarrier::complete_tx::bytes [%0], [%1], %2, [%3];"
        :: "r"(dst), "l"(src), "r"(bytes), "r"(mbar) : "memory");
}
#define MBARRIER_INIT(addr, cnt) \
    asm volatile("mbarrier.init.shared.b64 [%0], %1;" :: "r"((uint32_t)(addr)), "r"((uint32_t)(cnt)) : "memory")
#define MBARRIER_EXPECT_TX(addr, bytes) \
    asm volatile("mbarrier.arrive.expect_tx.shared.b64 _, [%0], %1;" \
        :: "r"((uint32_t)(addr)), "r"((uint32_t)(bytes)) : "memory")
#define MBARRIER_WAIT_PARITY(mbar_smem_addr, phase_parity) do { \
    uint32_t _mbar = (uint32_t)(mbar_smem_addr); \
    uint32_t _parity = (uint32_t)(phase_parity); \
    uint32_t _done; \
    asm volatile( \
        "{\n\t.reg .pred p;\n\t" \
        "mbarrier.try_wait.parity.acquire.cta.shared::cta.b64 p, [%1], %2;\n\t" \
        "selp.b32 %0, 1, 0, p;\n\t}" \
        : "=r"(_done) : "r"(_mbar), "r"(_parity) : "memory"); \
    if (!_done) { \
        asm volatile( \
            "{\n\t.reg .pred P1;\n\t" \
            "WAIT_LOOP_%=:\n\t" \
            "mbarrier.try_wait.parity.acquire.cta.shared::cta.b64 P1, [%0], %1, 0x989680;\n\t" \
            "@P1 bra.uni WAIT_DONE_%=;\n\t" \
            "bra.uni WAIT_LOOP_%=;\n\t" \
            "WAIT_DONE_%=:\n\t}" \
            :: "r"(_mbar), "r"(_parity) : "memory"); \
    } \
} while(0)
#define BAR1() asm volatile("bar.sync 1, 256;" ::: "memory")

__device__ __forceinline__ float sigf(float x) {
    return __fdividef(1.f, 1.f + __expf(-x));
}
__device__ __forceinline__ float tanh_fast(float x) {
    x = fminf(fmaxf(x, -15.f), 15.f);
    float e = __expf(2.f * x);
    return __fdividef(e - 1.f, e + 1.f);
}

__device__ __forceinline__ uint2 pack4h(float a, float b, float c, float d) {
    __half2 p0 = __floats2half2_rn(a, b);
    __half2 p1 = __floats2half2_rn(c, d);
    uint2 r;
    r.x = *(uint32_t*)&p0;
    r.y = *(uint32_t*)&p1;
    return r;
}

// ---------------- init / prep kernels ----------------
__global__ void init_state_kernel() {
    int i = blockIdx.x * blockDim.x + threadIdx.x;
    if (i < 65536) ((uint32_t*)g_hh2)[i] = 0u;   // 2 x 128KB
    if (i < 4) g_prod[i] = 0u;
    if (i == 4) g_cons = 0u;
}

__global__ void build_WW_kernel(const float* __restrict__ W_hh) {
    int i = blockIdx.x * blockDim.x + threadIdx.x;
    if (i < G_ * H_ / 4) {
        int row = i >> 8;
        int col4 = (i & 255) * 4;
        float4 w = *(const float4*)(W_hh + (size_t)row * 1024 + col4);
        *(uint2*)(g_WW + (size_t)row * 1024 + col4) = pack4h(w.x, w.y, w.z, w.w);
    }
}

__global__ void build_Wih_kernel(const float* __restrict__ W_ih) {
    int i = blockIdx.x * blockDim.x + threadIdx.x;
    if (i < G_ * D_ / 4) {
        int row = i >> 8;
        int col4 = (i & 255) * 4;
        float4 w = *(const float4*)(W_ih + (size_t)row * 1024 + col4);
        *(uint2*)(g_Wih + (size_t)row * 1024 + col4) = pack4h(w.x, w.y, w.z, w.w);
    }
}

__global__ void build_fA_kernel(const float* __restrict__ feature) {
    int i = blockIdx.x * blockDim.x + threadIdx.x;
    if (i < T_ * B_ * D_ / 4) {
        int k4 = (i & 255) * 4;
        int m = i >> 8;
        int tt = m >> 6, b = m & 63;
        float4 v = *(const float4*)(feature + ((size_t)b * T_ + tt) * D_ + k4);
        *(uint2*)(g_fh + (size_t)m * 1024 + k4) = pack4h(v.x, v.y, v.z, v.w);
    }
}

// ---------------- Phase A: x_gates GEMM via HMMA fp16 (single-pass W) ---------
static constexpr uint32_t XS_AH = 0;        // 16KB
static constexpr uint32_t XS_BH = 16384;    // 16KB
static constexpr uint32_t XS_STAGE = 32768;
static constexpr uint32_t XS_REQ = 2 * XS_STAGE + 1024;

__global__ __launch_bounds__(256, 1) void gemm_xg_tc(
    const float* __restrict__ b_ih, const float* __restrict__ b_hh)
{
    extern __shared__ char dsm_raw[];
    uint32_t raw = smem_to_u32(dsm_raw);
    uint32_t sbase = (raw + 1023u) & ~1023u;
    char* sm = dsm_raw + (sbase - raw);

    int tid = threadIdx.x;
    int wid = tid >> 5, lane = tid & 31;
    int m0 = blockIdx.x * 128;
    int n0 = blockIdx.y * 128;
    int wm = wid >> 1, wn = wid & 1;

    int q8 = lane >> 3, r8 = lane & 7;
    uint32_t a_lrow = (uint32_t)(r8 + (q8 & 1) * 8);
    uint32_t a_kb   = (uint32_t)((q8 >> 1) * 16);
    uint32_t b_lrow = (uint32_t)(r8 + (q8 >> 1) * 8);
    uint32_t b_kb   = (uint32_t)((q8 & 1) * 16);

    int srow = tid >> 3;
    int colB = (tid & 7) * 8;

    int r4 = lane >> 2, c4 = lane & 3;
    float2 bias2[8];
#pragma unroll
    for (int nt = 0; nt < 8; nt++) {
        int n = n0 + wn * 64 + nt * 8 + c4 * 2;
        bias2[nt] = make_float2(b_ih[n] + b_hh[n], b_ih[n + 1] + b_hh[n + 1]);
    }

    float acc[2][8][4];
#pragma unroll
    for (int mt = 0; mt < 2; mt++)
#pragma unroll
        for (int nt = 0; nt < 8; nt++)
#pragma unroll
            for (int i = 0; i < 4; i++) acc[mt][nt][i] = 0.f;

    {
#pragma unroll
        for (int i = 0; i < 4; i++) {
            int r = srow + 32 * i;
            uint32_t d = SWZ((uint32_t)(r * 128 + colB * 2));
            cp_async16(sbase + XS_AH + d, g_fh + (size_t)(m0 + r) * 1024 + colB);
            cp_async16(sbase + XS_BH + d, g_Wih + (size_t)(n0 + r) * 1024 + colB);
        }
        CP_COMMIT();
    }

#pragma unroll 1
    for (int c = 0; c < 16; c++) {
        uint32_t sb = sbase + (c & 1) * XS_STAGE;
        CP_WAIT(0);
        __syncthreads();
        if (c < 15) {
            int kc = (c + 1) * 64;
            uint32_t nb = (c & 1) ? 0u : XS_STAGE;
#pragma unroll
            for (int i = 0; i < 4; i++) {
                int r = srow + 32 * i;
                uint32_t d = nb + SWZ((uint32_t)(r * 128 + colB * 2));
                cp_async16(sbase + XS_AH + d, g_fh + (size_t)(m0 + r) * 1024 + kc + colB);
                cp_async16(sbase + XS_BH + d, g_Wih + (size_t)(n0 + r) * 1024 + kc + colB);
            }
            CP_COMMIT();
        }

#pragma unroll
        for (int kk = 0; kk < 4; kk++) {
            uint32_t koff = (uint32_t)(kk * 32) + a_kb;
            uint32_t kboff = (uint32_t)(kk * 32) + b_kb;
            uint32_t Ah[2][4], Bh[4][4];
#pragma unroll
            for (int mt = 0; mt < 2; mt++) {
                uint32_t rbase = (uint32_t)((wm * 32 + mt * 16 + a_lrow) * 128);
                ldsm_x4(Ah[mt][0], Ah[mt][1], Ah[mt][2], Ah[mt][3],
                        sb + XS_AH + SWZ(rbase + koff));
            }
#pragma unroll
            for (int ng = 0; ng < 4; ng++) {
                uint32_t rbase = (uint32_t)((wn * 64 + ng * 16 + b_lrow) * 128);
                ldsm_x4(Bh[ng][0], Bh[ng][1], Bh[ng][2], Bh[ng][3],
                        sb + XS_BH + SWZ(rbase + kboff));
            }
#pragma unroll
            for (int mt = 0; mt < 2; mt++)
#pragma unroll
                for (int ng = 0; ng < 4; ng++) {
                    hmma16816(acc[mt][ng * 2],     Ah[mt][0], Ah[mt][1], Ah[mt][2], Ah[mt][3], Bh[ng][0], Bh[ng][1]);
                    hmma16816(acc[mt][ng * 2 + 1], Ah[mt][0], Ah[mt][1], Ah[mt][2], Ah[mt][3], Bh[ng][2], Bh[ng][3]);
                }
        }
    }

#pragma unroll
    for (int mt = 0; mt < 2; mt++) {
        int row0 = m0 + wm * 32 + mt * 16 + r4;
#pragma unroll
        for (int nt = 0; nt < 8; nt++) {
            int n = n0 + wn * 64 + nt * 8 + c4 * 2;
            *(float2*)(g_xg + (size_t)row0 * G_ + n) =
                make_float2(acc[mt][nt][0] + bias2[nt].x, acc[mt][nt][1] + bias2[nt].y);
            *(float2*)(g_xg + (size_t)(row0 + 8) * G_ + n) =
                make_float2(acc[mt][nt][2] + bias2[nt].x, acc[mt][nt][3] + bias2[nt].y);
        }
    }
}

// ---------------- Phase B: persistent recurrence, producer-warp pipeline ------
// 128 blocks x 288 threads. Warps 0-7 compute; warp 8 lane 0 is the producer:
// it polls g_prod / slot-free and issues all cp.async.bulk into a 4-slot ring
// (slot = stage index i, mbarrier phase = t&1). Compute signals consumption
// via volatile shared s_done after a compute-only named barrier (bar.sync 1).
static constexpr uint32_t OFF_A  = 0;           // 4 slots x 32768 = 128KB (W staged here in prologue)
static constexpr uint32_t OFF_MB = 131072;      // 4 mbarriers
static constexpr uint32_t OFF_SD = 131104;      // volatile s_done (int)
static constexpr uint32_t OFF_S  = 131136;      // ssum [8][64][34] f32 = 69632
static constexpr uint32_t SMEM_USED = OFF_S + 8 * 64 * 34 * 4;
static constexpr uint32_t SMEM_REQ  = SMEM_USED + 1024;

__global__ __launch_bounds__(288, 1) void lstm_persistent(
    const int* __restrict__ seq_len, float* __restrict__ out)
{
    extern __shared__ char dsm_raw[];
    uint32_t raw = smem_to_u32(dsm_raw);
    uint32_t sbase = (raw + 1023u) & ~1023u;
    char* sm = dsm_raw + (sbase - raw);

    int tid = threadIdx.x;
    int wid = tid >> 5, lane = tid & 31;
    int bx = blockIdx.x;
    int j0 = bx * 8;
    int grp = bx >> 5;

    int q8 = lane >> 3, r8 = lane & 7;
    uint32_t a_lrow = (uint32_t)(r8 + (q8 & 1) * 8);
    uint32_t a_kb   = (uint32_t)((q8 >> 1) * 16);
    uint32_t b_lrow = (uint32_t)(r8 + (q8 >> 1) * 8);
    uint32_t b_kb   = (uint32_t)((q8 & 1) * 16);

    volatile int* sdone = (volatile int*)(sm + OFF_SD);
    if (tid == 0) {
#pragma unroll
        for (int s = 0; s < 4; s++) MBARRIER_INIT(sbase + OFF_MB + s * 8, 1);
        *sdone = 0;
    }

    int sg[4];
#pragma unroll
    for (int i = 0; i < 4; i++) sg[i] = (grp + 1 + i) & 3;

    // ---- prologue: stage W (fp16) into ring area, ldsm to regs (warps 0-7) ----
    uint32_t wr[4][2][4][2];
    if (tid < 256) {
        int rr = tid >> 3;
        int cb = (tid & 7) * 8;
        int gn = (rr >> 3) * H_ + j0 + (rr & 7);
        const __half* wrow = g_WW + (size_t)gn * 1024;
#pragma unroll
        for (int it = 0; it < 16; it++) {
            int col = it * 64 + cb;
            uint32_t soff = (uint32_t)((col >> 6) * 4096) +
                            SWZ((uint32_t)(rr * 128 + (col & 63) * 2));
            *(uint4*)(sm + OFF_A + soff) = *(const uint4*)(wrow + col);
        }
    }
    __syncthreads();
    if (tid < 256) {
#pragma unroll
        for (int i = 0; i < 4; i++)
#pragma unroll
            for (int kk = 0; kk < 2; kk++) {
                int scol = sg[i] * 256 + wid * 32 + kk * 16;
                uint32_t sub = (uint32_t)((scol >> 6) * 4096);
                uint32_t cin2 = (uint32_t)((scol & 63) * 2) + b_kb;
                ldsm_x4(wr[i][kk][0][0], wr[i][kk][0][1],
                        wr[i][kk][1][0], wr[i][kk][1][1],
                        sbase + OFF_A + sub + SWZ(b_lrow * 128 + cin2));
                ldsm_x4(wr[i][kk][2][0], wr[i][kk][2][1],
                        wr[i][kk][3][0], wr[i][kk][3][1],
                        sbase + OFF_A + sub + SWZ((b_lrow + 16) * 128 + cin2));
            }
    }
    __syncthreads();   // last CTA-wide sync; warps diverge below

    // within-stage A offsets (stage = 4 subtiles of 8KB)
    uint32_t asub0 = (uint32_t)(((wid * 32) >> 6) * 8192);
    uint32_t acin0 = (uint32_t)(((wid * 32) & 63) * 2) + a_kb;
    uint32_t asub1 = (uint32_t)(((wid * 32 + 16) >> 6) * 8192);
    uint32_t acin1 = (uint32_t)(((wid * 32 + 16) & 63) * 2) + a_kb;

    volatile unsigned* prod = (volatile unsigned*)g_prod;
    volatile unsigned* cons = (volatile unsigned*)&g_cons;
    float* ssum = (float*)(sm + OFF_S);

    if (wid < 8) {
        // ------------------ compute warps ------------------
        int eb0 = tid >> 3;
        int eb1 = eb0 + 32;
        int eu = tid & 7;
        int ej = j0 + eu;
        int sl0 = seq_len[eb0], sl1 = seq_len[eb1];
        float c0 = 0.f, c1 = 0.f;
        int hs = ej >> 8, hsub = (ej >> 6) & 3, hcin = ej & 63;
        uint32_t hbase = (uint32_t)((hs * 4 + hsub) * 8192);
        uint32_t hoff0 = hbase + SWZ((uint32_t)(eb0 * 128 + hcin * 2));
        uint32_t hoff1 = hbase + SWZ((uint32_t)(eb1 * 128 + hcin * 2));

#pragma unroll 1
        for (int t = 0; t < T_; t++) {
            uint8_t* __restrict__ hout2 = g_hh2[(t + 1) & 1];

            float xr0[4], xr1[4];
            {
                const float* xa = g_xg + ((size_t)t * B_ + eb0) * G_ + ej;
                const float* xb = g_xg + ((size_t)t * B_ + eb1) * G_ + ej;
#pragma unroll
                for (int g4 = 0; g4 < 4; g4++) { xr0[g4] = xa[g4 * H_]; xr1[g4] = xb[g4 * H_]; }
            }

            float acc[4][4][4];
#pragma unroll
            for (int mt = 0; mt < 4; mt++)
#pragma unroll
                for (int nt = 0; nt < 4; nt++)
#pragma unroll
                    for (int i = 0; i < 4; i++) acc[mt][nt][i] = 0.f;

#pragma unroll
            for (int i = 0; i < 4; i++) {
                int n = t * 4 + i;           // slot = i, phase = t&1
                MBARRIER_WAIT_PARITY(sbase + OFF_MB + i * 8, t & 1);
                if (i == 3 && tid == 0) atomicAdd(&g_cons, 1u);
                uint32_t abase = sbase + OFF_A + (uint32_t)(i * 32768);

#pragma unroll
                for (int kk = 0; kk < 2; kk++) {
                    uint32_t atile = abase + (kk ? asub1 : asub0);
                    uint32_t cin2  = kk ? acin1 : acin0;
                    uint32_t ah[4][4];
#pragma unroll
                    for (int mt = 0; mt < 4; mt++)
                        ldsm_x4(ah[mt][0], ah[mt][1], ah[mt][2], ah[mt][3],
                                atile + SWZ((mt * 16 + a_lrow) * 128 + cin2));
#pragma unroll
                    for (int mt = 0; mt < 4; mt++)
#pragma unroll
                        for (int nt = 0; nt < 4; nt++)
                            hmma16816(acc[mt][nt], ah[mt][0], ah[mt][1], ah[mt][2], ah[mt][3],
                                      wr[i][kk][nt][0], wr[i][kk][nt][1]);
                }
                BAR1();
                if (tid == 0) *sdone = n + 1;
            }

            // ---- partial store + merge ----
            {
                int r = lane >> 2, c4 = lane & 3;
                float* pp = ssum + wid * (64 * 34);
#pragma unroll
                for (int mt = 0; mt < 4; mt++)
#pragma unroll
                    for (int nt = 0; nt < 4; nt++) {
                        int b1 = mt * 16 + r, n = nt * 8 + c4 * 2;
                        *(float2*)(pp + b1 * 34 + n) =
                            make_float2(acc[mt][nt][0], acc[mt][nt][1]);
                        *(float2*)(pp + (b1 + 8) * 34 + n) =
                            make_float2(acc[mt][nt][2], acc[mt][nt][3]);
                    }
            }
            BAR1();

            if (tid == 0) {
                unsigned needc = 128u * (unsigned)t;
                while (*cons < needc) { }
            }
            BAR1();

            // ---- epilogue: compute + h store, publish, then out stores ----
            float hn_s[2];
#pragma unroll
            for (int it = 0; it < 2; it++) {
                int b = it ? eb1 : eb0;
                float gate[4];
#pragma unroll
                for (int g4 = 0; g4 < 4; g4++) {
                    int n = g4 * 8 + eu;
                    float s0 = 0.f;
#pragma unroll
                    for (int w = 0; w < 8; w++)
                        s0 += ssum[w * (64 * 34) + b * 34 + n];
                    gate[g4] = s0 + (it ? xr1[g4] : xr0[g4]);
                }
                float si = sigf(gate[0]);
                float sf = sigf(gate[1]);
                float tg = tanh_fast(gate[2]);
                float so = sigf(gate[3]);
                float cn = fmaf(sf, it ? c1 : c0, si * tg);
                if (it) c1 = cn; else c0 = cn;
                float hn = so * tanh_fast(cn);
                hn_s[it] = hn;
                *(__half*)(hout2 + (it ? hoff1 : hoff0)) = __float2half(hn);
            }

            __threadfence();
            BAR1();
            if (tid == 0) atomicAdd(&g_prod[grp], 1u);

            out[((size_t)eb0 * T_ + t) * H_ + ej] = (t < sl0) ? hn_s[0] : 0.f;
            out[((size_t)eb1 * T_ + t) * H_ + ej] = (t < sl1) ? hn_s[1] : 0.f;
        }
    } else if (lane == 0) {
        // ------------------ producer (warp 8, lane 0) ------------------
#pragma unroll 1
        for (int t = 0; t < T_; t++) {
            const uint8_t* hin2p = g_hh2[t & 1];
            unsigned needp = 32u * (unsigned)t;
#pragma unroll 1
            for (int i = 0; i < 4; i++) {
                int n = t * 4 + i;
                while (*sdone < n - 3) { }          // slot i free (use n-4 consumed)
                while (prod[sg[i]] < needp) { }     // source h published
                uint32_t mb = sbase + OFF_MB + (uint32_t)(i * 8);
                MBARRIER_EXPECT_TX(mb, 32768);
                cp_bulk_g2s(sbase + OFF_A + (uint32_t)(i * 32768),
                            hin2p + sg[i] * 32768, 32768, mb);
            }
        }
    }
}

extern "C" void kernel_launch(void* const* d_in, const int* in_sizes, int n_in,
                              void* d_out, int out_size)
{
    const float* feature = (const float*)d_in[0];
    const float* W_ih    = (const float*)d_in[1];
    const float* W_hh    = (const float*)d_in[2];
    const float* b_ih    = (const float*)d_in[3];
    const float* b_hh    = (const float*)d_in[4];
    const int*   seq_len = (const int*)d_in[5];
    float* out = (float*)d_out;

    cudaFuncSetAttribute(lstm_persistent, cudaFuncAttributeMaxDynamicSharedMemorySize,
                         SMEM_REQ);
    cudaFuncSetAttribute(gemm_xg_tc, cudaFuncAttributeMaxDynamicSharedMemorySize,
                         XS_REQ);

    init_state_kernel<<<(65536 + 255) / 256, 256>>>();
    build_WW_kernel<<<(G_ * H_ / 4 + 255) / 256, 256>>>(W_hh);
    build_Wih_kernel<<<(G_ * D_ / 4 + 255) / 256, 256>>>(W_ih);
    build_fA_kernel<<<(T_ * B_ * D_ / 4 + 255) / 256, 256>>>(feature);
    gemm_xg_tc<<<dim3(256, 32), 256, XS_REQ>>>(b_ih, b_hh);
    lstm_persistent<<<128, 288, SMEM_REQ>>>(seq_len, out);
}